// round 11
// baseline (speedup 1.0000x reference)
#include <cuda_runtime.h>
#include <cuda_bf16.h>
#include <math.h>
#include <stdint.h>

#define B_  16
#define NQ  1024
#define D_  512
#define H_  8
#define DH  64
#define M_  (B_*NQ)

__device__ float g_Qp[(size_t)M_*D_];
__device__ float g_O1[(size_t)M_*D_];
__device__ float g_O2[(size_t)M_*D_];
__device__ __nv_bfloat16 g_Qb[(size_t)M_*D_];
__device__ __nv_bfloat16 g_Kb[(size_t)M_*D_];
__device__ __nv_bfloat16 g_Vb[(size_t)M_*D_];
// bf16 split weights: [w][plane hi/lo][chunk k/16][n 0..511][8 words of bf16x2]
__device__ unsigned g_Wb[4][2][(size_t)32*512*8];

__device__ __forceinline__ unsigned pkbf(float lo, float hi) {
    unsigned r;
    asm("cvt.rn.bf16x2.f32 %0, %1, %2;" : "=r"(r) : "f"(hi), "f"(lo));
    return r;
}
__device__ __forceinline__ uint32_t sptr(const void* p) {
    return (uint32_t)__cvta_generic_to_shared(p);
}
__device__ __forceinline__ float ex2f(float x) {
    float r; asm("ex2.approx.f32 %0, %1;" : "=f"(r) : "f"(x)); return r;
}
__device__ __forceinline__ float hi_trunc(float x) {
    return __uint_as_float(__float_as_uint(x) & 0xFFFF0000u);
}
__device__ __forceinline__ unsigned pk_hi(float x0, float x1) {
    return __byte_perm(__float_as_uint(x0), __float_as_uint(x1), 0x7632);
}

#define MMA_BF16(acc, a, b0, b1) \
    asm volatile("mma.sync.aligned.m16n8k16.row.col.f32.bf16.bf16.f32 " \
        "{%0,%1,%2,%3}, {%4,%5,%6,%7}, {%8,%9}, {%0,%1,%2,%3};" \
        : "+f"(acc[0]), "+f"(acc[1]), "+f"(acc[2]), "+f"(acc[3]) \
        : "r"(a[0]), "r"(a[1]), "r"(a[2]), "r"(a[3]), "r"(b0), "r"(b1))

#define LDSM4(r, addr) \
    asm volatile("ldmatrix.sync.aligned.m8n8.x4.shared.b16 {%0,%1,%2,%3}, [%4];" \
        : "=r"(r[0]), "=r"(r[1]), "=r"(r[2]), "=r"(r[3]) : "r"(addr))

#define LDSM4T(r, addr) \
    asm volatile("ldmatrix.sync.aligned.m8n8.x4.trans.shared.b16 {%0,%1,%2,%3}, [%4];" \
        : "=r"(r[0]), "=r"(r[1]), "=r"(r[2]), "=r"(r[3]) : "r"(addr))

// ---------------- weight split hi/lo + transpose + k-tile (ONE launch) ----------------
__global__ void __launch_bounds__(256) trw2_k(
    const float* __restrict__ W0, const float* __restrict__ W1,
    const float* __restrict__ W2, const float* __restrict__ W3,
    unsigned* __restrict__ Wb)
{
    __shared__ unsigned th[16][33], tl[16][33];
    const int tx = threadIdx.x, ty = threadIdx.y;
    const int n0 = blockIdx.x * 32, k0 = blockIdx.y * 32;
    const int w  = blockIdx.z;
    const float* W = (w == 0) ? W0 : (w == 1) ? W1 : (w == 2) ? W2 : W3;

    for (int j = ty; j < 16; j += 8) {
        const int k = k0 + 2*j;
        const float a0 = W[(size_t)k * D_ + n0 + tx];
        const float a1 = W[(size_t)(k+1) * D_ + n0 + tx];
        th[j][tx] = pk_hi(a0, a1);
        tl[j][tx] = pkbf(a0 - hi_trunc(a0), a1 - hi_trunc(a1));
    }
    __syncthreads();
    unsigned* Wh = Wb + (size_t)w * 2 * 32*512*8;
    unsigned* Wl = Wh + (size_t)32*512*8;
    for (int j = ty; j < 16; j += 8) {
        const int k2g = (k0 >> 1) + j;
        const size_t idx = (size_t)(k2g >> 3) * (512*8) + (size_t)(n0 + tx) * 8 + (k2g & 7);
        Wh[idx] = th[j][tx];
        Wl[idx] = tl[j][tx];
    }
}

// ================= bf16x3 GEMM, type-outermost MMA order =================
#define SB2 12   // tile row stride in words

// epi: 0: (acc+bias)*mask[row]   1: acc+bias   2: A+relu(acc+bias)
__device__ __forceinline__ void gemm_b3_body(
    const float* __restrict__ A, const unsigned* __restrict__ Wbase,
    const float* __restrict__ bias, const float* __restrict__ mask,
    float* __restrict__ Cf, __nv_bfloat16* __restrict__ Cb, const int epi,
    unsigned (*Ah)[128][SB2], unsigned (*Al)[128][SB2],
    unsigned (*Bh)[128][SB2], unsigned (*Bl)[128][SB2])
{
    const int tid  = threadIdx.x;
    const int lane = tid & 31;
    const int wid  = tid >> 5;
    const int warp_m = (wid >> 1) * 32;
    const int warp_n = (wid & 1) * 64;
    const int bm = blockIdx.y * 128;
    const int bn = blockIdx.x * 128;
    const int gr = lane >> 2, gc = lane & 3;
    const int l15 = lane & 15;
    const int a_c = (lane & 16) ? 4 : 0;
    const int b_r = (lane & 16) ? 8 : 0;
    const int b_c = (lane & 8)  ? 4 : 0;
    const int l7  = lane & 7;

    const int arow = tid >> 2;
    const int acw  = (tid & 3) * 2;
    const float* Ap = A + (size_t)(bm + arow) * D_ + (tid & 3) * 4;

    const int bnr = tid >> 1;
    const int bh4 = (tid & 1) * 4;
    const unsigned* Wh = Wbase + (size_t)(bn + bnr) * 8 + bh4;
    const unsigned* Wl = Wh + (size_t)32*512*8;

    float acc[2][8][4];
    #pragma unroll
    for (int mt = 0; mt < 2; mt++)
        #pragma unroll
        for (int nt = 0; nt < 8; nt++)
            #pragma unroll
            for (int c = 0; c < 4; c++) acc[mt][nt][c] = 0.f;

    float4 ar0, ar1;
    uint4 bwh, bwl;

    ar0 = *(const float4*)(Ap);
    ar1 = *(const float4*)(Ap + (size_t)64 * D_);
    bwh = *(const uint4*)(Wh);
    bwl = *(const uint4*)(Wl);
    {
        *(uint2*)&Ah[0][arow][acw] = make_uint2(pk_hi(ar0.x, ar0.y), pk_hi(ar0.z, ar0.w));
        *(uint2*)&Al[0][arow][acw] = make_uint2(
            pkbf(ar0.x - hi_trunc(ar0.x), ar0.y - hi_trunc(ar0.y)),
            pkbf(ar0.z - hi_trunc(ar0.z), ar0.w - hi_trunc(ar0.w)));
        *(uint2*)&Ah[0][arow+64][acw] = make_uint2(pk_hi(ar1.x, ar1.y), pk_hi(ar1.z, ar1.w));
        *(uint2*)&Al[0][arow+64][acw] = make_uint2(
            pkbf(ar1.x - hi_trunc(ar1.x), ar1.y - hi_trunc(ar1.y)),
            pkbf(ar1.z - hi_trunc(ar1.z), ar1.w - hi_trunc(ar1.w)));
        *(uint4*)&Bh[0][bnr][bh4] = bwh;
        *(uint4*)&Bl[0][bnr][bh4] = bwl;
    }
    __syncthreads();

    for (int t = 0; t < 32; t++) {
        const int buf = t & 1;
        if (t + 1 < 32) {
            const int k0 = (t + 1) * 16;
            ar0 = *(const float4*)(Ap + k0);
            ar1 = *(const float4*)(Ap + (size_t)64 * D_ + k0);
            bwh = *(const uint4*)(Wh + (size_t)(t + 1) * (512*8));
            bwl = *(const uint4*)(Wl + (size_t)(t + 1) * (512*8));
        }

        unsigned afh[2][4], afl[2][4];
        #pragma unroll
        for (int mt = 0; mt < 2; mt++) {
            LDSM4(afh[mt], sptr(&Ah[buf][warp_m + mt*16 + l15][a_c]));
            LDSM4(afl[mt], sptr(&Al[buf][warp_m + mt*16 + l15][a_c]));
        }
        #pragma unroll
        for (int half = 0; half < 2; half++) {
            unsigned bfh[2][4], bfl[2][4];
            #pragma unroll
            for (int g = 0; g < 2; g++) {
                const int row = warp_n + (half*2 + g)*16 + l7 + b_r;
                LDSM4(bfh[g], sptr(&Bh[buf][row][b_c]));
                LDSM4(bfl[g], sptr(&Bl[buf][row][b_c]));
            }
            // pass 1: ah*wh  (8 independent accumulators)
            #pragma unroll
            for (int mt = 0; mt < 2; mt++)
                #pragma unroll
                for (int j = 0; j < 4; j++)
                    MMA_BF16(acc[mt][half*4 + j], afh[mt],
                             bfh[j>>1][(j&1)*2], bfh[j>>1][(j&1)*2+1]);
            // pass 2: al*wh
            #pragma unroll
            for (int mt = 0; mt < 2; mt++)
                #pragma unroll
                for (int j = 0; j < 4; j++)
                    MMA_BF16(acc[mt][half*4 + j], afl[mt],
                             bfh[j>>1][(j&1)*2], bfh[j>>1][(j&1)*2+1]);
            // pass 3: ah*wl
            #pragma unroll
            for (int mt = 0; mt < 2; mt++)
                #pragma unroll
                for (int j = 0; j < 4; j++)
                    MMA_BF16(acc[mt][half*4 + j], afh[mt],
                             bfl[j>>1][(j&1)*2], bfl[j>>1][(j&1)*2+1]);
        }

        if (t + 1 < 32) {
            const int nb = (t + 1) & 1;
            *(uint2*)&Ah[nb][arow][acw] = make_uint2(pk_hi(ar0.x, ar0.y), pk_hi(ar0.z, ar0.w));
            *(uint2*)&Al[nb][arow][acw] = make_uint2(
                pkbf(ar0.x - hi_trunc(ar0.x), ar0.y - hi_trunc(ar0.y)),
                pkbf(ar0.z - hi_trunc(ar0.z), ar0.w - hi_trunc(ar0.w)));
            *(uint2*)&Ah[nb][arow+64][acw] = make_uint2(pk_hi(ar1.x, ar1.y), pk_hi(ar1.z, ar1.w));
            *(uint2*)&Al[nb][arow+64][acw] = make_uint2(
                pkbf(ar1.x - hi_trunc(ar1.x), ar1.y - hi_trunc(ar1.y)),
                pkbf(ar1.z - hi_trunc(ar1.z), ar1.w - hi_trunc(ar1.w)));
            *(uint4*)&Bh[nb][bnr][bh4] = bwh;
            *(uint4*)&Bl[nb][bnr][bh4] = bwl;
            __syncthreads();
        }
    }

    #pragma unroll
    for (int mt = 0; mt < 2; mt++) {
        #pragma unroll
        for (int nt = 0; nt < 8; nt++) {
            const int row0 = bm + warp_m + mt * 16 + gr;
            const int row1 = row0 + 8;
            const int col  = bn + warp_n + nt * 8 + gc * 2;
            const float b0 = bias[col], b1 = bias[col + 1];
            float v0 = acc[mt][nt][0] + b0;
            float v1 = acc[mt][nt][1] + b1;
            float v2 = acc[mt][nt][2] + b0;
            float v3 = acc[mt][nt][3] + b1;
            if (epi == 0) {
                const float m0 = mask[row0], m1 = mask[row1];
                v0 *= m0; v1 *= m0; v2 *= m1; v3 *= m1;
            } else if (epi == 2) {
                const float2 r0 = *(const float2*)(A + (size_t)row0 * D_ + col);
                const float2 r1 = *(const float2*)(A + (size_t)row1 * D_ + col);
                v0 = r0.x + fmaxf(v0, 0.f);
                v1 = r0.y + fmaxf(v1, 0.f);
                v2 = r1.x + fmaxf(v2, 0.f);
                v3 = r1.y + fmaxf(v3, 0.f);
            }
            if (Cf) {
                *(float2*)&Cf[(size_t)row0 * D_ + col] = make_float2(v0, v1);
                *(float2*)&Cf[(size_t)row1 * D_ + col] = make_float2(v2, v3);
            }
            if (Cb) {
                *(unsigned*)&Cb[(size_t)row0 * D_ + col] = pkbf(v0, v1);
                *(unsigned*)&Cb[(size_t)row1 * D_ + col] = pkbf(v2, v3);
            }
        }
    }
}

// merged 3-projection GEMM
__global__ void __launch_bounds__(256, 2) gemm3_k(
    const float* __restrict__ Q, const float* __restrict__ Kin,
    const unsigned* __restrict__ Wb,
    const float* __restrict__ bq, const float* __restrict__ bk,
    const float* __restrict__ bv,
    const float* __restrict__ Qm, const float* __restrict__ Km,
    float* __restrict__ Qp,
    __nv_bfloat16* __restrict__ Qb, __nv_bfloat16* __restrict__ Kb,
    __nv_bfloat16* __restrict__ Vb)
{
    __shared__ unsigned Ah[2][128][SB2], Al[2][128][SB2];
    __shared__ unsigned Bh[2][128][SB2], Bl[2][128][SB2];
    const int z = blockIdx.z;
    const float* A    = (z == 0) ? Q  : Kin;
    const unsigned* W = Wb + (size_t)z * 2 * 32*512*8;
    const float* bias = (z == 0) ? bq : (z == 1) ? bk : bv;
    const float* mask = (z == 0) ? Qm : Km;
    float* Cf         = (z == 0) ? Qp : nullptr;
    __nv_bfloat16* Cb = (z == 0) ? Qb : (z == 1) ? Kb : Vb;
    const int epi     = (z == 2) ? 1 : 0;
    gemm_b3_body(A, W, bias, mask, Cf, Cb, epi, Ah, Al, Bh, Bl);
}

__global__ void __launch_bounds__(256, 2) gemmo_k(
    const float* __restrict__ A, const unsigned* __restrict__ Wb,
    const float* __restrict__ bias, float* __restrict__ C)
{
    __shared__ unsigned Ah[2][128][SB2], Al[2][128][SB2];
    __shared__ unsigned Bh[2][128][SB2], Bl[2][128][SB2];
    gemm_b3_body(A, Wb + (size_t)3 * 2 * 32*512*8, bias, nullptr, C, nullptr, 2,
                 Ah, Al, Bh, Bl);
}

// ================= bf16 attention (R9 + mask-in-exponent) =================
#define SH 72
#define ATT_SMEM ((128*SH + 2*64*SH + 2*64*SH)*2 + (128 + 2*64)*4)
#define C1_EXP 0.063758717f            // log2(e)/sqrt(512)
#define LOG2E  1.4426950408889634f

__global__ void __launch_bounds__(256, 2) attn_bf(
    const float* __restrict__ Qp, const __nv_bfloat16* __restrict__ Qbg,
    const __nv_bfloat16* __restrict__ Kbg, const __nv_bfloat16* __restrict__ Vbg,
    const float* __restrict__ Qm, const float* __restrict__ Km,
    float* __restrict__ O)
{
    extern __shared__ char smc[];
    __nv_bfloat16* Qs = (__nv_bfloat16*)smc;
    __nv_bfloat16* Ks = Qs + 128*SH;
    __nv_bfloat16* Vs = Ks + 2*64*SH;
    float* qms = (float*)(Vs + 2*64*SH);   // log2-domain query mask: 0 or -1e30
    float* kms = qms + 128;                // Km * log2e

    const int tid  = threadIdx.x;
    const int lane = tid & 31;
    const int wid  = tid >> 5;
    const int gr = lane >> 2, gc = lane & 3;
    const int l7  = lane & 7;
    const int l8  = (lane & 8)  ? 8 : 0;
    const int l16 = (lane & 16) ? 8 : 0;
    const int r0  = wid * 16;

    const int q0 = blockIdx.x * 128;
    const int b  = blockIdx.y;
    const int h  = blockIdx.z;
    const size_t base = (size_t)b * NQ * D_ + (size_t)h * DH;

    const int lrow = tid >> 4;
    const int lc4  = (tid & 15) * 4;

    #pragma unroll
    for (int p = 0; p < 8; p++) {
        const int row = p * 16 + lrow;
        *(uint2*)&Qs[row*SH + lc4] =
            *(const uint2*)(Qbg + base + (size_t)(q0 + row) * D_ + lc4);
    }
    if (tid < 128) qms[tid] = (Qm[(size_t)b*NQ + q0 + tid] > 0.5f) ? 0.f : -1e30f;

    uint2 kpre[4], vpre[4];
    #pragma unroll
    for (int p = 0; p < 4; p++) {
        const int row = p * 16 + lrow;
        kpre[p] = *(const uint2*)(Kbg + base + (size_t)row * D_ + lc4);
        vpre[p] = *(const uint2*)(Vbg + base + (size_t)row * D_ + lc4);
    }

    float oacc[8][4];
    #pragma unroll
    for (int nt = 0; nt < 8; nt++)
        #pragma unroll
        for (int c = 0; c < 4; c++) oacc[nt][c] = 0.f;
    float rsum0 = 0.f, rsum1 = 0.f;

    for (int kt = 0; kt < NQ/64; kt++) {
        const int buf = kt & 1;
        __nv_bfloat16* Kb = Ks + buf*64*SH;
        __nv_bfloat16* Vb = Vs + buf*64*SH;
        #pragma unroll
        for (int p = 0; p < 4; p++) {
            const int row = p * 16 + lrow;
            *(uint2*)&Kb[row*SH + lc4] = kpre[p];
            *(uint2*)&Vb[row*SH + lc4] = vpre[p];
        }
        if (tid < 64) kms[buf*64 + tid] = Km[(size_t)b*NQ + kt*64 + tid] * LOG2E;
        __syncthreads();

        if (kt + 1 < NQ/64) {
            #pragma unroll
            for (int p = 0; p < 4; p++)
                kpre[p] = *(const uint2*)(Kbg + base +
                    (size_t)((kt+1)*64 + p*16 + lrow) * D_ + lc4);
        }

        float sacc[8][4];
        #pragma unroll
        for (int nt = 0; nt < 8; nt++)
            #pragma unroll
            for (int c = 0; c < 4; c++) sacc[nt][c] = 0.f;

        #pragma unroll
        for (int ks = 0; ks < 4; ks++) {
            unsigned qf[4], bq[4][4];
            LDSM4(qf, sptr(&Qs[(r0 + l7 + l8)*SH + ks*16 + l16]));
            #pragma unroll
            for (int ntp = 0; ntp < 4; ntp++)
                LDSM4(bq[ntp], sptr(&Kb[(ntp*16 + l7 + l16)*SH + ks*16 + l8]));
            #pragma unroll
            for (int nt = 0; nt < 8; nt++)
                MMA_BF16(sacc[nt], qf, bq[nt>>1][(nt&1)*2], bq[nt>>1][(nt&1)*2+1]);
        }

        if (kt + 1 < NQ/64) {
            #pragma unroll
            for (int p = 0; p < 4; p++)
                vpre[p] = *(const uint2*)(Vbg + base +
                    (size_t)((kt+1)*64 + p*16 + lrow) * D_ + lc4);
        }

        unsigned xf[4][4];
        const float lg0 = qms[r0 + gr];
        const float lg1 = qms[r0 + 8 + gr];
        float p0 = 0.f, p1 = 0.f;
        #pragma unroll
        for (int nt = 0; nt < 8; nt++) {
            const int col = nt*8 + gc*2;
            const float km0 = kms[buf*64 + col];
            const float km1 = kms[buf*64 + col + 1];
            float y00 = ex2f(sacc[nt][0]*C1_EXP);
            float y01 = ex2f(sacc[nt][1]*C1_EXP);
            float y10 = ex2f(sacc[nt][2]*C1_EXP);
            float y11 = ex2f(sacc[nt][3]*C1_EXP);
            float x00 = ex2f(fmaf(y00, km0, lg0));
            float x01 = ex2f(fmaf(y01, km1, lg0));
            float x10 = ex2f(fmaf(y10, km0, lg1));
            float x11 = ex2f(fmaf(y11, km1, lg1));
            p0 += x00 + x01;
            p1 += x10 + x11;
            const int ksv = nt >> 1, pr = (nt & 1) * 2;
            xf[ksv][pr]     = pkbf(x00, x01);
            xf[ksv][pr + 1] = pkbf(x10, x11);
        }
        p0 += __shfl_xor_sync(0xffffffffu, p0, 1);
        p0 += __shfl_xor_sync(0xffffffffu, p0, 2);
        p1 += __shfl_xor_sync(0xffffffffu, p1, 1);
        p1 += __shfl_xor_sync(0xffffffffu, p1, 2);
        rsum0 += p0;
        rsum1 += p1;

        #pragma unroll
        for (int ksv = 0; ksv < 4; ksv++) {
            unsigned bv[4][4];
            #pragma unroll
            for (int ntp = 0; ntp < 4; ntp++)
                LDSM4T(bv[ntp], sptr(&Vb[(ksv*16 + l7 + l8)*SH + ntp*16 + l16]));
            #pragma unroll
            for (int nt = 0; nt < 8; nt++)
                MMA_BF16(oacc[nt], xf[ksv], bv[nt>>1][(nt&1)*2], bv[nt>>1][(nt&1)*2+1]);
        }
    }

    const float inv0 = 1.f / (rsum0 + 1e-8f);
    const float inv1 = 1.f / (rsum1 + 1e-8f);
    const int row0 = q0 + r0 + gr;
    const int row1 = row0 + 8;
    #pragma unroll
    for (int nt = 0; nt < 8; nt++) {
        const int col = nt*8 + gc*2;
        const float2 q0v = *(const float2*)(Qp + base + (size_t)row0*D_ + col);
        const float2 q1v = *(const float2*)(Qp + base + (size_t)row1*D_ + col);
        *(float2*)&O[base + (size_t)row0*D_ + col] =
            make_float2(q0v.x + oacc[nt][0]*inv0, q0v.y + oacc[nt][1]*inv0);
        *(float2*)&O[base + (size_t)row1*D_ + col] =
            make_float2(q1v.x + oacc[nt][2]*inv1, q1v.y + oacc[nt][3]*inv1);
    }
}

// ================= LayerNorm: warp per row =================
__global__ void __launch_bounds__(256) ln_w(
    const float* __restrict__ X, const float* __restrict__ g,
    const float* __restrict__ bb, float* __restrict__ Y)
{
    const int row  = blockIdx.x * 8 + (threadIdx.x >> 5);
    const int lane = threadIdx.x & 31;
    const float4* xr = (const float4*)(X + (size_t)row * D_);
    float4 v[4];
    float s = 0.f, s2 = 0.f;
    #pragma unroll
    for (int p = 0; p < 4; p++) {
        v[p] = xr[lane + 32*p];
        s  += v[p].x + v[p].y + v[p].z + v[p].w;
        s2 += v[p].x*v[p].x + v[p].y*v[p].y + v[p].z*v[p].z + v[p].w*v[p].w;
    }
    #pragma unroll
    for (int o = 16; o > 0; o >>= 1) {
        s  += __shfl_xor_sync(0xffffffffu, s,  o);
        s2 += __shfl_xor_sync(0xffffffffu, s2, o);
    }
    const float mean = s * (1.f/D_);
    const float var  = s2 * (1.f/D_) - mean*mean;
    const float inv  = rsqrtf(var + 1e-5f);
    float4* yr = (float4*)(Y + (size_t)row * D_);
    #pragma unroll
    for (int p = 0; p < 4; p++) {
        const float4 gv = ((const float4*)g)[lane + 32*p];
        const float4 bv = ((const float4*)bb)[lane + 32*p];
        float4 o;
        o.x = (v[p].x - mean)*inv*gv.x + bv.x;
        o.y = (v[p].y - mean)*inv*gv.y + bv.y;
        o.z = (v[p].z - mean)*inv*gv.z + bv.z;
        o.w = (v[p].w - mean)*inv*gv.w + bv.w;
        yr[lane + 32*p] = o;
    }
}

extern "C" void kernel_launch(void* const* d_in, const int* in_sizes, int n_in,
                              void* d_out, int out_size)
{
    const float* Q  = (const float*)d_in[0];
    const float* K  = (const float*)d_in[1];
    const float* Qm = (const float*)d_in[2];
    const float* Km = (const float*)d_in[3];
    const float* Wq = (const float*)d_in[4];
    const float* bq = (const float*)d_in[5];
    const float* Wk = (const float*)d_in[6];
    const float* bk = (const float*)d_in[7];
    const float* Wv = (const float*)d_in[8];
    const float* bv = (const float*)d_in[9];
    const float* Wo = (const float*)d_in[10];
    const float* bo = (const float*)d_in[11];
    const float* g0 = (const float*)d_in[12];
    const float* b0 = (const float*)d_in[13];
    const float* g1 = (const float*)d_in[14];
    const float* b1 = (const float*)d_in[15];
    float* out = (float*)d_out;

    float *pQp, *pO1, *pO2;
    __nv_bfloat16 *pQb, *pKb, *pVb;
    unsigned* pWb;
    cudaGetSymbolAddress((void**)&pQp, g_Qp);
    cudaGetSymbolAddress((void**)&pO1, g_O1);
    cudaGetSymbolAddress((void**)&pO2, g_O2);
    cudaGetSymbolAddress((void**)&pQb, g_Qb);
    cudaGetSymbolAddress((void**)&pKb, g_Kb);
    cudaGetSymbolAddress((void**)&pVb, g_Vb);
    cudaGetSymbolAddress((void**)&pWb, g_Wb);

    cudaFuncSetAttribute(attn_bf, cudaFuncAttributeMaxDynamicSharedMemorySize, ATT_SMEM);

    trw2_k<<<dim3(16, 16, 4), dim3(32, 8)>>>(Wq, Wk, Wv, Wo, pWb);

    dim3 gblk(256);
    dim3 g3(D_/128, M_/128, 3);
    gemm3_k<<<g3, gblk>>>(Q, K, pWb, bq, bk, bv, Qm, Km, pQp, pQb, pKb, pVb);

    dim3 agrid(NQ/128, B_, H_);
    attn_bf<<<agrid, 256, ATT_SMEM>>>(pQp, pQb, pKb, pVb, Qm, Km, pO1);

    ln_w<<<M_/8, 256>>>(pO1, g0, b0, pO2);
    gemmo_k<<<dim3(D_/128, M_/128), gblk>>>(pO2, pWb, bo, pQp);
    ln_w<<<M_/8, 256>>>(pQp, g1, b1, out);
}

// round 12
// speedup vs baseline: 1.0045x; 1.0045x over previous
#include <cuda_runtime.h>
#include <cuda_bf16.h>
#include <math.h>
#include <stdint.h>

#define B_  16
#define NQ  1024
#define D_  512
#define H_  8
#define DH  64
#define M_  (B_*NQ)

__device__ float g_Qp[(size_t)M_*D_];
__device__ float g_O1[(size_t)M_*D_];
__device__ float g_O2[(size_t)M_*D_];
__device__ __nv_bfloat16 g_Qb[(size_t)M_*D_];
__device__ __nv_bfloat16 g_Kb[(size_t)M_*D_];
__device__ __nv_bfloat16 g_Vb[(size_t)M_*D_];
// bf16 split weights: [w][plane hi/lo][chunk k/16][n 0..511][8 words of bf16x2]
__device__ unsigned g_Wb[4][2][(size_t)32*512*8];

__device__ __forceinline__ unsigned pkbf(float lo, float hi) {
    unsigned r;
    asm("cvt.rn.bf16x2.f32 %0, %1, %2;" : "=r"(r) : "f"(hi), "f"(lo));
    return r;
}
__device__ __forceinline__ uint32_t sptr(const void* p) {
    return (uint32_t)__cvta_generic_to_shared(p);
}
__device__ __forceinline__ float ex2f(float x) {
    float r; asm("ex2.approx.f32 %0, %1;" : "=f"(r) : "f"(x)); return r;
}
__device__ __forceinline__ float hi_trunc(float x) {
    return __uint_as_float(__float_as_uint(x) & 0xFFFF0000u);
}
__device__ __forceinline__ unsigned pk_hi(float x0, float x1) {
    return __byte_perm(__float_as_uint(x0), __float_as_uint(x1), 0x7632);
}

#define MMA_BF16(acc, a, b0, b1) \
    asm volatile("mma.sync.aligned.m16n8k16.row.col.f32.bf16.bf16.f32 " \
        "{%0,%1,%2,%3}, {%4,%5,%6,%7}, {%8,%9}, {%0,%1,%2,%3};" \
        : "+f"(acc[0]), "+f"(acc[1]), "+f"(acc[2]), "+f"(acc[3]) \
        : "r"(a[0]), "r"(a[1]), "r"(a[2]), "r"(a[3]), "r"(b0), "r"(b1))

#define LDSM4(r, addr) \
    asm volatile("ldmatrix.sync.aligned.m8n8.x4.shared.b16 {%0,%1,%2,%3}, [%4];" \
        : "=r"(r[0]), "=r"(r[1]), "=r"(r[2]), "=r"(r[3]) : "r"(addr))

#define LDSM4T(r, addr) \
    asm volatile("ldmatrix.sync.aligned.m8n8.x4.trans.shared.b16 {%0,%1,%2,%3}, [%4];" \
        : "=r"(r[0]), "=r"(r[1]), "=r"(r[2]), "=r"(r[3]) : "r"(addr))

// ---------------- weight split hi/lo + transpose + k-tile (ONE launch) ----------------
__global__ void __launch_bounds__(256) trw2_k(
    const float* __restrict__ W0, const float* __restrict__ W1,
    const float* __restrict__ W2, const float* __restrict__ W3,
    unsigned* __restrict__ Wb)
{
    __shared__ unsigned th[16][33], tl[16][33];
    const int tx = threadIdx.x, ty = threadIdx.y;
    const int n0 = blockIdx.x * 32, k0 = blockIdx.y * 32;
    const int w  = blockIdx.z;
    const float* W = (w == 0) ? W0 : (w == 1) ? W1 : (w == 2) ? W2 : W3;

    for (int j = ty; j < 16; j += 8) {
        const int k = k0 + 2*j;
        const float a0 = W[(size_t)k * D_ + n0 + tx];
        const float a1 = W[(size_t)(k+1) * D_ + n0 + tx];
        th[j][tx] = pk_hi(a0, a1);
        tl[j][tx] = pkbf(a0 - hi_trunc(a0), a1 - hi_trunc(a1));
    }
    __syncthreads();
    unsigned* Wh = Wb + (size_t)w * 2 * 32*512*8;
    unsigned* Wl = Wh + (size_t)32*512*8;
    for (int j = ty; j < 16; j += 8) {
        const int k2g = (k0 >> 1) + j;
        const size_t idx = (size_t)(k2g >> 3) * (512*8) + (size_t)(n0 + tx) * 8 + (k2g & 7);
        Wh[idx] = th[j][tx];
        Wl[idx] = tl[j][tx];
    }
}

// ================= bf16x3 GEMM, type-outermost MMA order =================
#define SB2 12   // tile row stride in words

// epi: 0: (acc+bias)*mask[row]   1: acc+bias   2: A+relu(acc+bias)
__device__ __forceinline__ void gemm_b3_body(
    const float* __restrict__ A, const unsigned* __restrict__ Wbase,
    const float* __restrict__ bias, const float* __restrict__ mask,
    float* __restrict__ Cf, __nv_bfloat16* __restrict__ Cb, const int epi,
    unsigned (*Ah)[128][SB2], unsigned (*Al)[128][SB2],
    unsigned (*Bh)[128][SB2], unsigned (*Bl)[128][SB2])
{
    const int tid  = threadIdx.x;
    const int lane = tid & 31;
    const int wid  = tid >> 5;
    const int warp_m = (wid >> 1) * 32;
    const int warp_n = (wid & 1) * 64;
    const int bm = blockIdx.y * 128;
    const int bn = blockIdx.x * 128;
    const int gr = lane >> 2, gc = lane & 3;
    const int l15 = lane & 15;
    const int a_c = (lane & 16) ? 4 : 0;
    const int b_r = (lane & 16) ? 8 : 0;
    const int b_c = (lane & 8)  ? 4 : 0;
    const int l7  = lane & 7;

    const int arow = tid >> 2;
    const int acw  = (tid & 3) * 2;
    const float* Ap = A + (size_t)(bm + arow) * D_ + (tid & 3) * 4;

    const int bnr = tid >> 1;
    const int bh4 = (tid & 1) * 4;
    const unsigned* Wh = Wbase + (size_t)(bn + bnr) * 8 + bh4;
    const unsigned* Wl = Wh + (size_t)32*512*8;

    float acc[2][8][4];
    #pragma unroll
    for (int mt = 0; mt < 2; mt++)
        #pragma unroll
        for (int nt = 0; nt < 8; nt++)
            #pragma unroll
            for (int c = 0; c < 4; c++) acc[mt][nt][c] = 0.f;

    float4 ar0, ar1;
    uint4 bwh, bwl;

    ar0 = *(const float4*)(Ap);
    ar1 = *(const float4*)(Ap + (size_t)64 * D_);
    bwh = *(const uint4*)(Wh);
    bwl = *(const uint4*)(Wl);
    {
        *(uint2*)&Ah[0][arow][acw] = make_uint2(pk_hi(ar0.x, ar0.y), pk_hi(ar0.z, ar0.w));
        *(uint2*)&Al[0][arow][acw] = make_uint2(
            pkbf(ar0.x - hi_trunc(ar0.x), ar0.y - hi_trunc(ar0.y)),
            pkbf(ar0.z - hi_trunc(ar0.z), ar0.w - hi_trunc(ar0.w)));
        *(uint2*)&Ah[0][arow+64][acw] = make_uint2(pk_hi(ar1.x, ar1.y), pk_hi(ar1.z, ar1.w));
        *(uint2*)&Al[0][arow+64][acw] = make_uint2(
            pkbf(ar1.x - hi_trunc(ar1.x), ar1.y - hi_trunc(ar1.y)),
            pkbf(ar1.z - hi_trunc(ar1.z), ar1.w - hi_trunc(ar1.w)));
        *(uint4*)&Bh[0][bnr][bh4] = bwh;
        *(uint4*)&Bl[0][bnr][bh4] = bwl;
    }
    __syncthreads();

    for (int t = 0; t < 32; t++) {
        const int buf = t & 1;
        if (t + 1 < 32) {
            const int k0 = (t + 1) * 16;
            ar0 = *(const float4*)(Ap + k0);
            ar1 = *(const float4*)(Ap + (size_t)64 * D_ + k0);
            bwh = *(const uint4*)(Wh + (size_t)(t + 1) * (512*8));
            bwl = *(const uint4*)(Wl + (size_t)(t + 1) * (512*8));
        }

        unsigned afh[2][4], afl[2][4];
        #pragma unroll
        for (int mt = 0; mt < 2; mt++) {
            LDSM4(afh[mt], sptr(&Ah[buf][warp_m + mt*16 + l15][a_c]));
            LDSM4(afl[mt], sptr(&Al[buf][warp_m + mt*16 + l15][a_c]));
        }
        #pragma unroll
        for (int half = 0; half < 2; half++) {
            unsigned bfh[2][4], bfl[2][4];
            #pragma unroll
            for (int g = 0; g < 2; g++) {
                const int row = warp_n + (half*2 + g)*16 + l7 + b_r;
                LDSM4(bfh[g], sptr(&Bh[buf][row][b_c]));
                LDSM4(bfl[g], sptr(&Bl[buf][row][b_c]));
            }
            // pass 1: ah*wh  (8 independent accumulators)
            #pragma unroll
            for (int mt = 0; mt < 2; mt++)
                #pragma unroll
                for (int j = 0; j < 4; j++)
                    MMA_BF16(acc[mt][half*4 + j], afh[mt],
                             bfh[j>>1][(j&1)*2], bfh[j>>1][(j&1)*2+1]);
            // pass 2: al*wh
            #pragma unroll
            for (int mt = 0; mt < 2; mt++)
                #pragma unroll
                for (int j = 0; j < 4; j++)
                    MMA_BF16(acc[mt][half*4 + j], afl[mt],
                             bfh[j>>1][(j&1)*2], bfh[j>>1][(j&1)*2+1]);
            // pass 3: ah*wl
            #pragma unroll
            for (int mt = 0; mt < 2; mt++)
                #pragma unroll
                for (int j = 0; j < 4; j++)
                    MMA_BF16(acc[mt][half*4 + j], afh[mt],
                             bfl[j>>1][(j&1)*2], bfl[j>>1][(j&1)*2+1]);
        }

        if (t + 1 < 32) {
            const int nb = (t + 1) & 1;
            *(uint2*)&Ah[nb][arow][acw] = make_uint2(pk_hi(ar0.x, ar0.y), pk_hi(ar0.z, ar0.w));
            *(uint2*)&Al[nb][arow][acw] = make_uint2(
                pkbf(ar0.x - hi_trunc(ar0.x), ar0.y - hi_trunc(ar0.y)),
                pkbf(ar0.z - hi_trunc(ar0.z), ar0.w - hi_trunc(ar0.w)));
            *(uint2*)&Ah[nb][arow+64][acw] = make_uint2(pk_hi(ar1.x, ar1.y), pk_hi(ar1.z, ar1.w));
            *(uint2*)&Al[nb][arow+64][acw] = make_uint2(
                pkbf(ar1.x - hi_trunc(ar1.x), ar1.y - hi_trunc(ar1.y)),
                pkbf(ar1.z - hi_trunc(ar1.z), ar1.w - hi_trunc(ar1.w)));
            *(uint4*)&Bh[nb][bnr][bh4] = bwh;
            *(uint4*)&Bl[nb][bnr][bh4] = bwl;
            __syncthreads();
        }
    }

    #pragma unroll
    for (int mt = 0; mt < 2; mt++) {
        #pragma unroll
        for (int nt = 0; nt < 8; nt++) {
            const int row0 = bm + warp_m + mt * 16 + gr;
            const int row1 = row0 + 8;
            const int col  = bn + warp_n + nt * 8 + gc * 2;
            const float b0 = bias[col], b1 = bias[col + 1];
            float v0 = acc[mt][nt][0] + b0;
            float v1 = acc[mt][nt][1] + b1;
            float v2 = acc[mt][nt][2] + b0;
            float v3 = acc[mt][nt][3] + b1;
            if (epi == 0) {
                const float m0 = mask[row0], m1 = mask[row1];
                v0 *= m0; v1 *= m0; v2 *= m1; v3 *= m1;
            } else if (epi == 2) {
                const float2 r0 = *(const float2*)(A + (size_t)row0 * D_ + col);
                const float2 r1 = *(const float2*)(A + (size_t)row1 * D_ + col);
                v0 = r0.x + fmaxf(v0, 0.f);
                v1 = r0.y + fmaxf(v1, 0.f);
                v2 = r1.x + fmaxf(v2, 0.f);
                v3 = r1.y + fmaxf(v3, 0.f);
            }
            if (Cf) {
                *(float2*)&Cf[(size_t)row0 * D_ + col] = make_float2(v0, v1);
                *(float2*)&Cf[(size_t)row1 * D_ + col] = make_float2(v2, v3);
            }
            if (Cb) {
                *(unsigned*)&Cb[(size_t)row0 * D_ + col] = pkbf(v0, v1);
                *(unsigned*)&Cb[(size_t)row1 * D_ + col] = pkbf(v2, v3);
            }
        }
    }
}

// merged 3-projection GEMM
__global__ void __launch_bounds__(256, 2) gemm3_k(
    const float* __restrict__ Q, const float* __restrict__ Kin,
    const unsigned* __restrict__ Wb,
    const float* __restrict__ bq, const float* __restrict__ bk,
    const float* __restrict__ bv,
    const float* __restrict__ Qm, const float* __restrict__ Km,
    float* __restrict__ Qp,
    __nv_bfloat16* __restrict__ Qb, __nv_bfloat16* __restrict__ Kb,
    __nv_bfloat16* __restrict__ Vb)
{
    __shared__ unsigned Ah[2][128][SB2], Al[2][128][SB2];
    __shared__ unsigned Bh[2][128][SB2], Bl[2][128][SB2];
    const int z = blockIdx.z;
    const float* A    = (z == 0) ? Q  : Kin;
    const unsigned* W = Wb + (size_t)z * 2 * 32*512*8;
    const float* bias = (z == 0) ? bq : (z == 1) ? bk : bv;
    const float* mask = (z == 0) ? Qm : Km;
    float* Cf         = (z == 0) ? Qp : nullptr;
    __nv_bfloat16* Cb = (z == 0) ? Qb : (z == 1) ? Kb : Vb;
    const int epi     = (z == 2) ? 1 : 0;
    gemm_b3_body(A, W, bias, mask, Cf, Cb, epi, Ah, Al, Bh, Bl);
}

__global__ void __launch_bounds__(256, 2) gemmo_k(
    const float* __restrict__ A, const unsigned* __restrict__ Wb,
    const float* __restrict__ bias, float* __restrict__ C)
{
    __shared__ unsigned Ah[2][128][SB2], Al[2][128][SB2];
    __shared__ unsigned Bh[2][128][SB2], Bl[2][128][SB2];
    gemm_b3_body(A, Wb + (size_t)3 * 2 * 32*512*8, bias, nullptr, C, nullptr, 2,
                 Ah, Al, Bh, Bl);
}

// ================= bf16 attention (R9 + mask-in-exponent) =================
#define SH 72
#define ATT_SMEM ((128*SH + 2*64*SH + 2*64*SH)*2 + (128 + 2*64)*4)
#define C1_EXP 0.063758717f            // log2(e)/sqrt(512)
#define LOG2E  1.4426950408889634f

__global__ void __launch_bounds__(256, 2) attn_bf(
    const float* __restrict__ Qp, const __nv_bfloat16* __restrict__ Qbg,
    const __nv_bfloat16* __restrict__ Kbg, const __nv_bfloat16* __restrict__ Vbg,
    const float* __restrict__ Qm, const float* __restrict__ Km,
    float* __restrict__ O)
{
    extern __shared__ char smc[];
    __nv_bfloat16* Qs = (__nv_bfloat16*)smc;
    __nv_bfloat16* Ks = Qs + 128*SH;
    __nv_bfloat16* Vs = Ks + 2*64*SH;
    float* qms = (float*)(Vs + 2*64*SH);   // log2-domain query mask: 0 or -1e30
    float* kms = qms + 128;                // Km * log2e

    const int tid  = threadIdx.x;
    const int lane = tid & 31;
    const int wid  = tid >> 5;
    const int gr = lane >> 2, gc = lane & 3;
    const int l7  = lane & 7;
    const int l8  = (lane & 8)  ? 8 : 0;
    const int l16 = (lane & 16) ? 8 : 0;
    const int r0  = wid * 16;

    const int q0 = blockIdx.x * 128;
    const int b  = blockIdx.y;
    const int h  = blockIdx.z;
    const size_t base = (size_t)b * NQ * D_ + (size_t)h * DH;

    const int lrow = tid >> 4;
    const int lc4  = (tid & 15) * 4;

    #pragma unroll
    for (int p = 0; p < 8; p++) {
        const int row = p * 16 + lrow;
        *(uint2*)&Qs[row*SH + lc4] =
            *(const uint2*)(Qbg + base + (size_t)(q0 + row) * D_ + lc4);
    }
    if (tid < 128) qms[tid] = (Qm[(size_t)b*NQ + q0 + tid] > 0.5f) ? 0.f : -1e30f;

    uint2 kpre[4], vpre[4];
    #pragma unroll
    for (int p = 0; p < 4; p++) {
        const int row = p * 16 + lrow;
        kpre[p] = *(const uint2*)(Kbg + base + (size_t)row * D_ + lc4);
        vpre[p] = *(const uint2*)(Vbg + base + (size_t)row * D_ + lc4);
    }

    float oacc[8][4];
    #pragma unroll
    for (int nt = 0; nt < 8; nt++)
        #pragma unroll
        for (int c = 0; c < 4; c++) oacc[nt][c] = 0.f;
    float rsum0 = 0.f, rsum1 = 0.f;

    for (int kt = 0; kt < NQ/64; kt++) {
        const int buf = kt & 1;
        __nv_bfloat16* Kb = Ks + buf*64*SH;
        __nv_bfloat16* Vb = Vs + buf*64*SH;
        #pragma unroll
        for (int p = 0; p < 4; p++) {
            const int row = p * 16 + lrow;
            *(uint2*)&Kb[row*SH + lc4] = kpre[p];
            *(uint2*)&Vb[row*SH + lc4] = vpre[p];
        }
        if (tid < 64) kms[buf*64 + tid] = Km[(size_t)b*NQ + kt*64 + tid] * LOG2E;
        __syncthreads();

        if (kt + 1 < NQ/64) {
            #pragma unroll
            for (int p = 0; p < 4; p++)
                kpre[p] = *(const uint2*)(Kbg + base +
                    (size_t)((kt+1)*64 + p*16 + lrow) * D_ + lc4);
        }

        float sacc[8][4];
        #pragma unroll
        for (int nt = 0; nt < 8; nt++)
            #pragma unroll
            for (int c = 0; c < 4; c++) sacc[nt][c] = 0.f;

        #pragma unroll
        for (int ks = 0; ks < 4; ks++) {
            unsigned qf[4], bq[4][4];
            LDSM4(qf, sptr(&Qs[(r0 + l7 + l8)*SH + ks*16 + l16]));
            #pragma unroll
            for (int ntp = 0; ntp < 4; ntp++)
                LDSM4(bq[ntp], sptr(&Kb[(ntp*16 + l7 + l16)*SH + ks*16 + l8]));
            #pragma unroll
            for (int nt = 0; nt < 8; nt++)
                MMA_BF16(sacc[nt], qf, bq[nt>>1][(nt&1)*2], bq[nt>>1][(nt&1)*2+1]);
        }

        if (kt + 1 < NQ/64) {
            #pragma unroll
            for (int p = 0; p < 4; p++)
                vpre[p] = *(const uint2*)(Vbg + base +
                    (size_t)((kt+1)*64 + p*16 + lrow) * D_ + lc4);
        }

        unsigned xf[4][4];
        const float lg0 = qms[r0 + gr];
        const float lg1 = qms[r0 + 8 + gr];
        float p0 = 0.f, p1 = 0.f;
        #pragma unroll
        for (int nt = 0; nt < 8; nt++) {
            const int col = nt*8 + gc*2;
            const float km0 = kms[buf*64 + col];
            const float km1 = kms[buf*64 + col + 1];
            float y00 = ex2f(sacc[nt][0]*C1_EXP);
            float y01 = ex2f(sacc[nt][1]*C1_EXP);
            float y10 = ex2f(sacc[nt][2]*C1_EXP);
            float y11 = ex2f(sacc[nt][3]*C1_EXP);
            float x00 = ex2f(fmaf(y00, km0, lg0));
            float x01 = ex2f(fmaf(y01, km1, lg0));
            float x10 = ex2f(fmaf(y10, km0, lg1));
            float x11 = ex2f(fmaf(y11, km1, lg1));
            p0 += x00 + x01;
            p1 += x10 + x11;
            const int ksv = nt >> 1, pr = (nt & 1) * 2;
            xf[ksv][pr]     = pkbf(x00, x01);
            xf[ksv][pr + 1] = pkbf(x10, x11);
        }
        p0 += __shfl_xor_sync(0xffffffffu, p0, 1);
        p0 += __shfl_xor_sync(0xffffffffu, p0, 2);
        p1 += __shfl_xor_sync(0xffffffffu, p1, 1);
        p1 += __shfl_xor_sync(0xffffffffu, p1, 2);
        rsum0 += p0;
        rsum1 += p1;

        #pragma unroll
        for (int ksv = 0; ksv < 4; ksv++) {
            unsigned bv[4][4];
            #pragma unroll
            for (int ntp = 0; ntp < 4; ntp++)
                LDSM4T(bv[ntp], sptr(&Vb[(ksv*16 + l7 + l8)*SH + ntp*16 + l16]));
            #pragma unroll
            for (int nt = 0; nt < 8; nt++)
                MMA_BF16(oacc[nt], xf[ksv], bv[nt>>1][(nt&1)*2], bv[nt>>1][(nt&1)*2+1]);
        }
    }

    const float inv0 = 1.f / (rsum0 + 1e-8f);
    const float inv1 = 1.f / (rsum1 + 1e-8f);
    const int row0 = q0 + r0 + gr;
    const int row1 = row0 + 8;
    #pragma unroll
    for (int nt = 0; nt < 8; nt++) {
        const int col = nt*8 + gc*2;
        const float2 q0v = *(const float2*)(Qp + base + (size_t)row0*D_ + col);
        const float2 q1v = *(const float2*)(Qp + base + (size_t)row1*D_ + col);
        *(float2*)&O[base + (size_t)row0*D_ + col] =
            make_float2(q0v.x + oacc[nt][0]*inv0, q0v.y + oacc[nt][1]*inv0);
        *(float2*)&O[base + (size_t)row1*D_ + col] =
            make_float2(q1v.x + oacc[nt][2]*inv1, q1v.y + oacc[nt][3]*inv1);
    }
}

// ================= LayerNorm: warp per row =================
__global__ void __launch_bounds__(256) ln_w(
    const float* __restrict__ X, const float* __restrict__ g,
    const float* __restrict__ bb, float* __restrict__ Y)
{
    const int row  = blockIdx.x * 8 + (threadIdx.x >> 5);
    const int lane = threadIdx.x & 31;
    const float4* xr = (const float4*)(X + (size_t)row * D_);
    float4 v[4];
    float s = 0.f, s2 = 0.f;
    #pragma unroll
    for (int p = 0; p < 4; p++) {
        v[p] = xr[lane + 32*p];
        s  += v[p].x + v[p].y + v[p].z + v[p].w;
        s2 += v[p].x*v[p].x + v[p].y*v[p].y + v[p].z*v[p].z + v[p].w*v[p].w;
    }
    #pragma unroll
    for (int o = 16; o > 0; o >>= 1) {
        s  += __shfl_xor_sync(0xffffffffu, s,  o);
        s2 += __shfl_xor_sync(0xffffffffu, s2, o);
    }
    const float mean = s * (1.f/D_);
    const float var  = s2 * (1.f/D_) - mean*mean;
    const float inv  = rsqrtf(var + 1e-5f);
    float4* yr = (float4*)(Y + (size_t)row * D_);
    #pragma unroll
    for (int p = 0; p < 4; p++) {
        const float4 gv = ((const float4*)g)[lane + 32*p];
        const float4 bv = ((const float4*)bb)[lane + 32*p];
        float4 o;
        o.x = (v[p].x - mean)*inv*gv.x + bv.x;
        o.y = (v[p].y - mean)*inv*gv.y + bv.y;
        o.z = (v[p].z - mean)*inv*gv.z + bv.z;
        o.w = (v[p].w - mean)*inv*gv.w + bv.w;
        yr[lane + 32*p] = o;
    }
}

extern "C" void kernel_launch(void* const* d_in, const int* in_sizes, int n_in,
                              void* d_out, int out_size)
{
    const float* Q  = (const float*)d_in[0];
    const float* K  = (const float*)d_in[1];
    const float* Qm = (const float*)d_in[2];
    const float* Km = (const float*)d_in[3];
    const float* Wq = (const float*)d_in[4];
    const float* bq = (const float*)d_in[5];
    const float* Wk = (const float*)d_in[6];
    const float* bk = (const float*)d_in[7];
    const float* Wv = (const float*)d_in[8];
    const float* bv = (const float*)d_in[9];
    const float* Wo = (const float*)d_in[10];
    const float* bo = (const float*)d_in[11];
    const float* g0 = (const float*)d_in[12];
    const float* b0 = (const float*)d_in[13];
    const float* g1 = (const float*)d_in[14];
    const float* b1 = (const float*)d_in[15];
    float* out = (float*)d_out;

    float *pQp, *pO1, *pO2;
    __nv_bfloat16 *pQb, *pKb, *pVb;
    unsigned* pWb;
    cudaGetSymbolAddress((void**)&pQp, g_Qp);
    cudaGetSymbolAddress((void**)&pO1, g_O1);
    cudaGetSymbolAddress((void**)&pO2, g_O2);
    cudaGetSymbolAddress((void**)&pQb, g_Qb);
    cudaGetSymbolAddress((void**)&pKb, g_Kb);
    cudaGetSymbolAddress((void**)&pVb, g_Vb);
    cudaGetSymbolAddress((void**)&pWb, g_Wb);

    cudaFuncSetAttribute(attn_bf, cudaFuncAttributeMaxDynamicSharedMemorySize, ATT_SMEM);

    trw2_k<<<dim3(16, 16, 4), dim3(32, 8)>>>(Wq, Wk, Wv, Wo, pWb);

    dim3 gblk(256);
    dim3 g3(D_/128, M_/128, 3);
    gemm3_k<<<g3, gblk>>>(Q, K, pWb, bq, bk, bv, Qm, Km, pQp, pQb, pKb, pVb);

    dim3 agrid(NQ/128, B_, H_);
    attn_bf<<<agrid, 256, ATT_SMEM>>>(pQp, pQb, pKb, pVb, Qm, Km, pO1);

    ln_w<<<M_/8, 256>>>(pO1, g0, b0, pO2);
    gemmo_k<<<dim3(D_/128, M_/128), gblk>>>(pO2, pWb, bo, pQp);
    ln_w<<<M_/8, 256>>>(pQp, g1, b1, out);
}

// round 13
// speedup vs baseline: 1.1050x; 1.1001x over previous
#include <cuda_runtime.h>
#include <cuda_bf16.h>
#include <math.h>
#include <stdint.h>

#define B_  16
#define NQ  1024
#define D_  512
#define H_  8
#define DH  64
#define M_  (B_*NQ)

__device__ float g_Qp[(size_t)M_*D_];
__device__ float g_O1[(size_t)M_*D_];
__device__ float g_mu[(size_t)M_];
__device__ float g_iv[(size_t)M_];
__device__ __nv_bfloat16 g_Qb[(size_t)M_*D_];
__device__ __nv_bfloat16 g_Kb[(size_t)M_*D_];
__device__ __nv_bfloat16 g_Vb[(size_t)M_*D_];

__device__ __forceinline__ unsigned f2tf32(float x) {
    unsigned u;
    asm("cvt.rna.tf32.f32 %0, %1;" : "=r"(u) : "f"(x));
    return u;
}
__device__ __forceinline__ unsigned pkbf(float lo, float hi) {
    unsigned r;
    asm("cvt.rn.bf16x2.f32 %0, %1, %2;" : "=r"(r) : "f"(hi), "f"(lo));
    return r;
}
__device__ __forceinline__ uint32_t sptr(const void* p) {
    return (uint32_t)__cvta_generic_to_shared(p);
}
__device__ __forceinline__ float ex2f(float x) {
    float r; asm("ex2.approx.f32 %0, %1;" : "=f"(r) : "f"(x)); return r;
}

#define MMA_TF32(acc, a0,a1,a2,a3, b0,b1) \
    asm volatile("mma.sync.aligned.m16n8k8.row.col.f32.tf32.tf32.f32 " \
        "{%0,%1,%2,%3}, {%4,%5,%6,%7}, {%8,%9}, {%0,%1,%2,%3};" \
        : "+f"(acc[0]), "+f"(acc[1]), "+f"(acc[2]), "+f"(acc[3]) \
        : "r"(a0), "r"(a1), "r"(a2), "r"(a3), "r"(b0), "r"(b1))

#define MMA_BF16(acc, a, b0, b1) \
    asm volatile("mma.sync.aligned.m16n8k16.row.col.f32.bf16.bf16.f32 " \
        "{%0,%1,%2,%3}, {%4,%5,%6,%7}, {%8,%9}, {%0,%1,%2,%3};" \
        : "+f"(acc[0]), "+f"(acc[1]), "+f"(acc[2]), "+f"(acc[3]) \
        : "r"(a[0]), "r"(a[1]), "r"(a[2]), "r"(a[3]), "r"(b0), "r"(b1))

#define LDSM4(r, addr) \
    asm volatile("ldmatrix.sync.aligned.m8n8.x4.shared.b16 {%0,%1,%2,%3}, [%4];" \
        : "=r"(r[0]), "=r"(r[1]), "=r"(r[2]), "=r"(r[3]) : "r"(addr))

#define LDSM4T(r, addr) \
    asm volatile("ldmatrix.sync.aligned.m8n8.x4.trans.shared.b16 {%0,%1,%2,%3}, [%4];" \
        : "=r"(r[0]), "=r"(r[1]), "=r"(r[2]), "=r"(r[3]) : "r"(addr))

// ================= TF32 GEMM body (R4/R9-proven), optional fused input-LN =================
#define TBM 128
#define TBN 128
#define TBK 16
#define GST 20

// epi: 0: (acc+bias)*mask[row]   1: acc+bias   2: LN(A)+relu(acc+bias)  (FUSE_LN)
template<bool FUSE_LN>
__device__ __forceinline__ void gemm_body(
    const float* __restrict__ A, const float* __restrict__ W,
    const float* __restrict__ bias, const float* __restrict__ mask,
    const float* __restrict__ mu, const float* __restrict__ iv,
    const float* __restrict__ lng, const float* __restrict__ lnb,
    float* __restrict__ Cf, __nv_bfloat16* __restrict__ Cb, const int epi,
    unsigned (*As)[TBM][GST], unsigned (*Bs)[TBN][GST])
{
    const int N = D_, K = D_;
    const int tid  = threadIdx.x;
    const int lane = tid & 31;
    const int wid  = tid >> 5;
    const int warp_m = (wid >> 1) * 32;
    const int warp_n = (wid & 1) * 64;
    const int bm = blockIdx.y * TBM;
    const int bn = blockIdx.x * TBN;
    const int gr = lane >> 2, gc = lane & 3;
    const int l7 = lane & 7;
    const int a_l8  = (lane & 8)  ? 8 : 0;
    const int a_l16 = (lane & 16) ? 4 : 0;
    const int b_l8  = (lane & 8)  ? 4 : 0;
    const int b_l16 = (lane & 16) ? 8 : 0;

    const int arow = tid >> 2;
    const int acol = (tid & 3) * 4;
    const float* Ap = A + (size_t)(bm + arow) * K + acol;

    const int bnl  = tid & 127;
    const int kq2  = tid >> 7;
    const float* Wp = W + bn + bnl;

    // per-row LN stats for the two rows this thread fills
    float mu0 = 0.f, iv0 = 1.f, mu1 = 0.f, iv1 = 1.f;
    if (FUSE_LN) {
        mu0 = mu[bm + arow];      iv0 = iv[bm + arow];
        mu1 = mu[bm + arow + 64]; iv1 = iv[bm + arow + 64];
    }

    float acc[2][8][4];
    #pragma unroll
    for (int mt = 0; mt < 2; mt++)
        #pragma unroll
        for (int nt = 0; nt < 8; nt++)
            #pragma unroll
            for (int c = 0; c < 4; c++) acc[mt][nt][c] = 0.f;

    float4 ar0, ar1, lgv, lbv;
    float bpre[2][4];

    ar0 = *(const float4*)(Ap);
    ar1 = *(const float4*)(Ap + (size_t)64 * K);
    if (FUSE_LN) {
        lgv = *(const float4*)(lng + acol);
        lbv = *(const float4*)(lnb + acol);
    }
    #pragma unroll
    for (int it = 0; it < 2; it++) {
        const int k = (kq2 + 2*it) * 4;
        #pragma unroll
        for (int j = 0; j < 4; j++)
            bpre[it][j] = Wp[(size_t)(k + j) * N];
    }
    {
        if (FUSE_LN) {
            ar0.x = (ar0.x - mu0)*iv0*lgv.x + lbv.x;
            ar0.y = (ar0.y - mu0)*iv0*lgv.y + lbv.y;
            ar0.z = (ar0.z - mu0)*iv0*lgv.z + lbv.z;
            ar0.w = (ar0.w - mu0)*iv0*lgv.w + lbv.w;
            ar1.x = (ar1.x - mu1)*iv1*lgv.x + lbv.x;
            ar1.y = (ar1.y - mu1)*iv1*lgv.y + lbv.y;
            ar1.z = (ar1.z - mu1)*iv1*lgv.z + lbv.z;
            ar1.w = (ar1.w - mu1)*iv1*lgv.w + lbv.w;
        }
        *(uint4*)&As[0][arow][acol] =
            make_uint4(f2tf32(ar0.x), f2tf32(ar0.y), f2tf32(ar0.z), f2tf32(ar0.w));
        *(uint4*)&As[0][arow+64][acol] =
            make_uint4(f2tf32(ar1.x), f2tf32(ar1.y), f2tf32(ar1.z), f2tf32(ar1.w));
        #pragma unroll
        for (int it = 0; it < 2; it++)
            *(uint4*)&Bs[0][bnl][(kq2 + 2*it)*4] =
                make_uint4(f2tf32(bpre[it][0]), f2tf32(bpre[it][1]),
                           f2tf32(bpre[it][2]), f2tf32(bpre[it][3]));
    }
    __syncthreads();

    const int NT = K / TBK;
    for (int t = 0; t < NT; t++) {
        const int buf = t & 1;
        if (t + 1 < NT) {
            const int k0 = (t + 1) * TBK;
            ar0 = *(const float4*)(Ap + k0);
            ar1 = *(const float4*)(Ap + (size_t)64 * K + k0);
            if (FUSE_LN) {
                lgv = *(const float4*)(lng + k0 + acol);
                lbv = *(const float4*)(lnb + k0 + acol);
            }
            #pragma unroll
            for (int it = 0; it < 2; it++) {
                const int k = k0 + (kq2 + 2*it) * 4;
                #pragma unroll
                for (int j = 0; j < 4; j++)
                    bpre[it][j] = Wp[(size_t)(k + j) * N];
            }
        }

        #pragma unroll
        for (int ks = 0; ks < 2; ks++) {
            const int k0 = ks * 8;
            unsigned af[2][4], bf[4][4];
            #pragma unroll
            for (int mt = 0; mt < 2; mt++)
                LDSM4(af[mt], sptr(&As[buf][warp_m + mt*16 + a_l8 + l7][k0 + a_l16]));
            #pragma unroll
            for (int ntp = 0; ntp < 4; ntp++)
                LDSM4(bf[ntp], sptr(&Bs[buf][warp_n + ntp*16 + b_l16 + l7][k0 + b_l8]));
            #pragma unroll
            for (int mt = 0; mt < 2; mt++)
                #pragma unroll
                for (int nt = 0; nt < 8; nt++)
                    MMA_TF32(acc[mt][nt], af[mt][0], af[mt][1], af[mt][2], af[mt][3],
                             bf[nt>>1][(nt&1)*2], bf[nt>>1][(nt&1)*2+1]);
        }

        if (t + 1 < NT) {
            const int nb = (t + 1) & 1;
            if (FUSE_LN) {
                ar0.x = (ar0.x - mu0)*iv0*lgv.x + lbv.x;
                ar0.y = (ar0.y - mu0)*iv0*lgv.y + lbv.y;
                ar0.z = (ar0.z - mu0)*iv0*lgv.z + lbv.z;
                ar0.w = (ar0.w - mu0)*iv0*lgv.w + lbv.w;
                ar1.x = (ar1.x - mu1)*iv1*lgv.x + lbv.x;
                ar1.y = (ar1.y - mu1)*iv1*lgv.y + lbv.y;
                ar1.z = (ar1.z - mu1)*iv1*lgv.z + lbv.z;
                ar1.w = (ar1.w - mu1)*iv1*lgv.w + lbv.w;
            }
            *(uint4*)&As[nb][arow][acol] =
                make_uint4(f2tf32(ar0.x), f2tf32(ar0.y), f2tf32(ar0.z), f2tf32(ar0.w));
            *(uint4*)&As[nb][arow+64][acol] =
                make_uint4(f2tf32(ar1.x), f2tf32(ar1.y), f2tf32(ar1.z), f2tf32(ar1.w));
            #pragma unroll
            for (int it = 0; it < 2; it++)
                *(uint4*)&Bs[nb][bnl][(kq2 + 2*it)*4] =
                    make_uint4(f2tf32(bpre[it][0]), f2tf32(bpre[it][1]),
                               f2tf32(bpre[it][2]), f2tf32(bpre[it][3]));
            __syncthreads();
        }
    }

    #pragma unroll
    for (int mt = 0; mt < 2; mt++) {
        float emu0 = 0.f, eiv0 = 1.f, emu1 = 0.f, eiv1 = 1.f;
        if (FUSE_LN && epi == 2) {
            const int r0i = bm + warp_m + mt * 16 + gr;
            emu0 = mu[r0i];     eiv0 = iv[r0i];
            emu1 = mu[r0i + 8]; eiv1 = iv[r0i + 8];
        }
        #pragma unroll
        for (int nt = 0; nt < 8; nt++) {
            const int row0 = bm + warp_m + mt * 16 + gr;
            const int row1 = row0 + 8;
            const int col  = bn + warp_n + nt * 8 + gc * 2;
            const float b0 = bias[col], b1 = bias[col + 1];
            float v0 = acc[mt][nt][0] + b0;
            float v1 = acc[mt][nt][1] + b1;
            float v2 = acc[mt][nt][2] + b0;
            float v3 = acc[mt][nt][3] + b1;
            if (epi == 0) {
                const float m0 = mask[row0], m1 = mask[row1];
                v0 *= m0; v1 *= m0; v2 *= m1; v3 *= m1;
            } else if (epi == 2) {
                float2 r0 = *(const float2*)(A + (size_t)row0 * K + col);
                float2 r1 = *(const float2*)(A + (size_t)row1 * K + col);
                if (FUSE_LN) {
                    const float2 gv = *(const float2*)(lng + col);
                    const float2 bv = *(const float2*)(lnb + col);
                    r0.x = (r0.x - emu0)*eiv0*gv.x + bv.x;
                    r0.y = (r0.y - emu0)*eiv0*gv.y + bv.y;
                    r1.x = (r1.x - emu1)*eiv1*gv.x + bv.x;
                    r1.y = (r1.y - emu1)*eiv1*gv.y + bv.y;
                }
                v0 = r0.x + fmaxf(v0, 0.f);
                v1 = r0.y + fmaxf(v1, 0.f);
                v2 = r1.x + fmaxf(v2, 0.f);
                v3 = r1.y + fmaxf(v3, 0.f);
            }
            if (Cf) {
                *(float2*)&Cf[(size_t)row0 * N + col] = make_float2(v0, v1);
                *(float2*)&Cf[(size_t)row1 * N + col] = make_float2(v2, v3);
            }
            if (Cb) {
                *(unsigned*)&Cb[(size_t)row0 * N + col] = pkbf(v0, v1);
                *(unsigned*)&Cb[(size_t)row1 * N + col] = pkbf(v2, v3);
            }
        }
    }
}

// merged 3-projection GEMM
__global__ void __launch_bounds__(256, 2) gemm3_k(
    const float* __restrict__ Q, const float* __restrict__ Kin,
    const float* __restrict__ Wq, const float* __restrict__ Wk,
    const float* __restrict__ Wv,
    const float* __restrict__ bq, const float* __restrict__ bk,
    const float* __restrict__ bv,
    const float* __restrict__ Qm, const float* __restrict__ Km,
    float* __restrict__ Qp,
    __nv_bfloat16* __restrict__ Qb, __nv_bfloat16* __restrict__ Kb,
    __nv_bfloat16* __restrict__ Vb)
{
    __shared__ unsigned As[2][TBM][GST];
    __shared__ unsigned Bs[2][TBN][GST];
    const int z = blockIdx.z;
    const float* A    = (z == 0) ? Q  : Kin;
    const float* W    = (z == 0) ? Wq : (z == 1) ? Wk : Wv;
    const float* bias = (z == 0) ? bq : (z == 1) ? bk : bv;
    const float* mask = (z == 0) ? Qm : Km;
    float* Cf         = (z == 0) ? Qp : nullptr;
    __nv_bfloat16* Cb = (z == 0) ? Qb : (z == 1) ? Kb : Vb;
    const int epi     = (z == 2) ? 1 : 0;
    gemm_body<false>(A, W, bias, mask, nullptr, nullptr, nullptr, nullptr,
                     Cf, Cb, epi, As, Bs);
}

// Wo projection with fused input-LayerNorm (A = pre-LN O1, stats in mu/iv)
__global__ void __launch_bounds__(256, 2) gemmo_k(
    const float* __restrict__ A, const float* __restrict__ W,
    const float* __restrict__ bias,
    const float* __restrict__ mu, const float* __restrict__ iv,
    const float* __restrict__ lng, const float* __restrict__ lnb,
    float* __restrict__ C)
{
    __shared__ unsigned As[2][TBM][GST];
    __shared__ unsigned Bs[2][TBN][GST];
    gemm_body<true>(A, W, bias, nullptr, mu, iv, lng, lnb,
                    C, nullptr, 2, As, Bs);
}

// ================= LN stats: warp per row (mean + invstd only) =================
__global__ void __launch_bounds__(256) lnstat_k(
    const float* __restrict__ X, float* __restrict__ mu, float* __restrict__ iv)
{
    const int row  = blockIdx.x * 8 + (threadIdx.x >> 5);
    const int lane = threadIdx.x & 31;
    const float4* xr = (const float4*)(X + (size_t)row * D_);
    float s = 0.f, s2 = 0.f;
    #pragma unroll
    for (int p = 0; p < 4; p++) {
        const float4 v = xr[lane + 32*p];
        s  += v.x + v.y + v.z + v.w;
        s2 += v.x*v.x + v.y*v.y + v.z*v.z + v.w*v.w;
    }
    #pragma unroll
    for (int o = 16; o > 0; o >>= 1) {
        s  += __shfl_xor_sync(0xffffffffu, s,  o);
        s2 += __shfl_xor_sync(0xffffffffu, s2, o);
    }
    if (lane == 0) {
        const float mean = s * (1.f/D_);
        const float var  = s2 * (1.f/D_) - mean*mean;
        mu[row] = mean;
        iv[row] = rsqrtf(var + 1e-5f);
    }
}

// ================= bf16 attention (R9 + mask-in-exponent) =================
#define SH 72
#define ATT_SMEM ((128*SH + 2*64*SH + 2*64*SH)*2 + (128 + 2*64)*4)
#define C1_EXP 0.063758717f            // log2(e)/sqrt(512)
#define LOG2E  1.4426950408889634f

__global__ void __launch_bounds__(256, 2) attn_bf(
    const float* __restrict__ Qp, const __nv_bfloat16* __restrict__ Qbg,
    const __nv_bfloat16* __restrict__ Kbg, const __nv_bfloat16* __restrict__ Vbg,
    const float* __restrict__ Qm, const float* __restrict__ Km,
    float* __restrict__ O)
{
    extern __shared__ char smc[];
    __nv_bfloat16* Qs = (__nv_bfloat16*)smc;
    __nv_bfloat16* Ks = Qs + 128*SH;
    __nv_bfloat16* Vs = Ks + 2*64*SH;
    float* qms = (float*)(Vs + 2*64*SH);   // log2-domain query mask: 0 or -1e30
    float* kms = qms + 128;                // Km * log2e

    const int tid  = threadIdx.x;
    const int lane = tid & 31;
    const int wid  = tid >> 5;
    const int gr = lane >> 2, gc = lane & 3;
    const int l7  = lane & 7;
    const int l8  = (lane & 8)  ? 8 : 0;
    const int l16 = (lane & 16) ? 8 : 0;
    const int r0  = wid * 16;

    const int q0 = blockIdx.x * 128;
    const int b  = blockIdx.y;
    const int h  = blockIdx.z;
    const size_t base = (size_t)b * NQ * D_ + (size_t)h * DH;

    const int lrow = tid >> 4;
    const int lc4  = (tid & 15) * 4;

    #pragma unroll
    for (int p = 0; p < 8; p++) {
        const int row = p * 16 + lrow;
        *(uint2*)&Qs[row*SH + lc4] =
            *(const uint2*)(Qbg + base + (size_t)(q0 + row) * D_ + lc4);
    }
    if (tid < 128) qms[tid] = (Qm[(size_t)b*NQ + q0 + tid] > 0.5f) ? 0.f : -1e30f;

    uint2 kpre[4], vpre[4];
    #pragma unroll
    for (int p = 0; p < 4; p++) {
        const int row = p * 16 + lrow;
        kpre[p] = *(const uint2*)(Kbg + base + (size_t)row * D_ + lc4);
        vpre[p] = *(const uint2*)(Vbg + base + (size_t)row * D_ + lc4);
    }

    float oacc[8][4];
    #pragma unroll
    for (int nt = 0; nt < 8; nt++)
        #pragma unroll
        for (int c = 0; c < 4; c++) oacc[nt][c] = 0.f;
    float rsum0 = 0.f, rsum1 = 0.f;

    for (int kt = 0; kt < NQ/64; kt++) {
        const int buf = kt & 1;
        __nv_bfloat16* Kb = Ks + buf*64*SH;
        __nv_bfloat16* Vb = Vs + buf*64*SH;
        #pragma unroll
        for (int p = 0; p < 4; p++) {
            const int row = p * 16 + lrow;
            *(uint2*)&Kb[row*SH + lc4] = kpre[p];
            *(uint2*)&Vb[row*SH + lc4] = vpre[p];
        }
        if (tid < 64) kms[buf*64 + tid] = Km[(size_t)b*NQ + kt*64 + tid] * LOG2E;
        __syncthreads();

        if (kt + 1 < NQ/64) {
            #pragma unroll
            for (int p = 0; p < 4; p++)
                kpre[p] = *(const uint2*)(Kbg + base +
                    (size_t)((kt+1)*64 + p*16 + lrow) * D_ + lc4);
        }

        float sacc[8][4];
        #pragma unroll
        for (int nt = 0; nt < 8; nt++)
            #pragma unroll
            for (int c = 0; c < 4; c++) sacc[nt][c] = 0.f;

        #pragma unroll
        for (int ks = 0; ks < 4; ks++) {
            unsigned qf[4], bq[4][4];
            LDSM4(qf, sptr(&Qs[(r0 + l7 + l8)*SH + ks*16 + l16]));
            #pragma unroll
            for (int ntp = 0; ntp < 4; ntp++)
                LDSM4(bq[ntp], sptr(&Kb[(ntp*16 + l7 + l16)*SH + ks*16 + l8]));
            #pragma unroll
            for (int nt = 0; nt < 8; nt++)
                MMA_BF16(sacc[nt], qf, bq[nt>>1][(nt&1)*2], bq[nt>>1][(nt&1)*2+1]);
        }

        if (kt + 1 < NQ/64) {
            #pragma unroll
            for (int p = 0; p < 4; p++)
                vpre[p] = *(const uint2*)(Vbg + base +
                    (size_t)((kt+1)*64 + p*16 + lrow) * D_ + lc4);
        }

        unsigned xf[4][4];
        const float lg0 = qms[r0 + gr];
        const float lg1 = qms[r0 + 8 + gr];
        float p0 = 0.f, p1 = 0.f;
        #pragma unroll
        for (int nt = 0; nt < 8; nt++) {
            const int col = nt*8 + gc*2;
            const float km0 = kms[buf*64 + col];
            const float km1 = kms[buf*64 + col + 1];
            float y00 = ex2f(sacc[nt][0]*C1_EXP);
            float y01 = ex2f(sacc[nt][1]*C1_EXP);
            float y10 = ex2f(sacc[nt][2]*C1_EXP);
            float y11 = ex2f(sacc[nt][3]*C1_EXP);
            float x00 = ex2f(fmaf(y00, km0, lg0));
            float x01 = ex2f(fmaf(y01, km1, lg0));
            float x10 = ex2f(fmaf(y10, km0, lg1));
            float x11 = ex2f(fmaf(y11, km1, lg1));
            p0 += x00 + x01;
            p1 += x10 + x11;
            const int ksv = nt >> 1, pr = (nt & 1) * 2;
            xf[ksv][pr]     = pkbf(x00, x01);
            xf[ksv][pr + 1] = pkbf(x10, x11);
        }
        p0 += __shfl_xor_sync(0xffffffffu, p0, 1);
        p0 += __shfl_xor_sync(0xffffffffu, p0, 2);
        p1 += __shfl_xor_sync(0xffffffffu, p1, 1);
        p1 += __shfl_xor_sync(0xffffffffu, p1, 2);
        rsum0 += p0;
        rsum1 += p1;

        #pragma unroll
        for (int ksv = 0; ksv < 4; ksv++) {
            unsigned bv[4][4];
            #pragma unroll
            for (int ntp = 0; ntp < 4; ntp++)
                LDSM4T(bv[ntp], sptr(&Vb[(ksv*16 + l7 + l8)*SH + ntp*16 + l16]));
            #pragma unroll
            for (int nt = 0; nt < 8; nt++)
                MMA_BF16(oacc[nt], xf[ksv], bv[nt>>1][(nt&1)*2], bv[nt>>1][(nt&1)*2+1]);
        }
    }

    const float inv0 = 1.f / (rsum0 + 1e-8f);
    const float inv1 = 1.f / (rsum1 + 1e-8f);
    const int row0 = q0 + r0 + gr;
    const int row1 = row0 + 8;
    #pragma unroll
    for (int nt = 0; nt < 8; nt++) {
        const int col = nt*8 + gc*2;
        const float2 q0v = *(const float2*)(Qp + base + (size_t)row0*D_ + col);
        const float2 q1v = *(const float2*)(Qp + base + (size_t)row1*D_ + col);
        *(float2*)&O[base + (size_t)row0*D_ + col] =
            make_float2(q0v.x + oacc[nt][0]*inv0, q0v.y + oacc[nt][1]*inv0);
        *(float2*)&O[base + (size_t)row1*D_ + col] =
            make_float2(q1v.x + oacc[nt][2]*inv1, q1v.y + oacc[nt][3]*inv1);
    }
}

// ================= LayerNorm (final): warp per row =================
__global__ void __launch_bounds__(256) ln_w(
    const float* __restrict__ X, const float* __restrict__ g,
    const float* __restrict__ bb, float* __restrict__ Y)
{
    const int row  = blockIdx.x * 8 + (threadIdx.x >> 5);
    const int lane = threadIdx.x & 31;
    const float4* xr = (const float4*)(X + (size_t)row * D_);
    float4 v[4];
    float s = 0.f, s2 = 0.f;
    #pragma unroll
    for (int p = 0; p < 4; p++) {
        v[p] = xr[lane + 32*p];
        s  += v[p].x + v[p].y + v[p].z + v[p].w;
        s2 += v[p].x*v[p].x + v[p].y*v[p].y + v[p].z*v[p].z + v[p].w*v[p].w;
    }
    #pragma unroll
    for (int o = 16; o > 0; o >>= 1) {
        s  += __shfl_xor_sync(0xffffffffu, s,  o);
        s2 += __shfl_xor_sync(0xffffffffu, s2, o);
    }
    const float mean = s * (1.f/D_);
    const float var  = s2 * (1.f/D_) - mean*mean;
    const float inv  = rsqrtf(var + 1e-5f);
    float4* yr = (float4*)(Y + (size_t)row * D_);
    #pragma unroll
    for (int p = 0; p < 4; p++) {
        const float4 gv = ((const float4*)g)[lane + 32*p];
        const float4 bv = ((const float4*)bb)[lane + 32*p];
        float4 o;
        o.x = (v[p].x - mean)*inv*gv.x + bv.x;
        o.y = (v[p].y - mean)*inv*gv.y + bv.y;
        o.z = (v[p].z - mean)*inv*gv.z + bv.z;
        o.w = (v[p].w - mean)*inv*gv.w + bv.w;
        yr[lane + 32*p] = o;
    }
}

extern "C" void kernel_launch(void* const* d_in, const int* in_sizes, int n_in,
                              void* d_out, int out_size)
{
    const float* Q  = (const float*)d_in[0];
    const float* K  = (const float*)d_in[1];
    const float* Qm = (const float*)d_in[2];
    const float* Km = (const float*)d_in[3];
    const float* Wq = (const float*)d_in[4];
    const float* bq = (const float*)d_in[5];
    const float* Wk = (const float*)d_in[6];
    const float* bk = (const float*)d_in[7];
    const float* Wv = (const float*)d_in[8];
    const float* bv = (const float*)d_in[9];
    const float* Wo = (const float*)d_in[10];
    const float* bo = (const float*)d_in[11];
    const float* g0 = (const float*)d_in[12];
    const float* b0 = (const float*)d_in[13];
    const float* g1 = (const float*)d_in[14];
    const float* b1 = (const float*)d_in[15];
    float* out = (float*)d_out;

    float *pQp, *pO1, *pMu, *pIv;
    __nv_bfloat16 *pQb, *pKb, *pVb;
    cudaGetSymbolAddress((void**)&pQp, g_Qp);
    cudaGetSymbolAddress((void**)&pO1, g_O1);
    cudaGetSymbolAddress((void**)&pMu, g_mu);
    cudaGetSymbolAddress((void**)&pIv, g_iv);
    cudaGetSymbolAddress((void**)&pQb, g_Qb);
    cudaGetSymbolAddress((void**)&pKb, g_Kb);
    cudaGetSymbolAddress((void**)&pVb, g_Vb);

    cudaFuncSetAttribute(attn_bf, cudaFuncAttributeMaxDynamicSharedMemorySize, ATT_SMEM);

    dim3 gblk(256);
    dim3 g3(D_/TBN, M_/TBM, 3);
    gemm3_k<<<g3, gblk>>>(Q, K, Wq, Wk, Wv, bq, bk, bv, Qm, Km, pQp, pQb, pKb, pVb);

    dim3 agrid(NQ/128, B_, H_);
    attn_bf<<<agrid, 256, ATT_SMEM>>>(pQp, pQb, pKb, pVb, Qm, Km, pO1);

    lnstat_k<<<M_/8, 256>>>(pO1, pMu, pIv);
    gemmo_k<<<dim3(D_/TBN, M_/TBM), gblk>>>(pO1, Wo, bo, pMu, pIv, g0, b0, pQp);
    ln_w<<<M_/8, 256>>>(pQp, g1, b1, out);
}

// round 14
// speedup vs baseline: 1.3416x; 1.2141x over previous
#include <cuda_runtime.h>
#include <cuda_bf16.h>
#include <cuda_fp16.h>
#include <math.h>
#include <stdint.h>

#define B_  16
#define NQ  1024
#define D_  512
#define H_  8
#define DH  64
#define M_  (B_*NQ)

__device__ float g_Qp[(size_t)M_*D_];
__device__ float g_O1[(size_t)M_*D_];
__device__ float g_O2[(size_t)M_*D_];
__device__ __nv_bfloat16 g_Qb[(size_t)M_*D_];
__device__ __nv_bfloat16 g_Kb[(size_t)M_*D_];
__device__ __nv_bfloat16 g_Vb[(size_t)M_*D_];

__device__ __forceinline__ unsigned pkbf(float lo, float hi) {
    unsigned r;
    asm("cvt.rn.bf16x2.f32 %0, %1, %2;" : "=r"(r) : "f"(hi), "f"(lo));
    return r;
}
__device__ __forceinline__ unsigned pkhf(float lo, float hi) {
    unsigned r;
    asm("cvt.rn.f16x2.f32 %0, %1, %2;" : "=r"(r) : "f"(hi), "f"(lo));
    return r;
}
__device__ __forceinline__ uint32_t sptr(const void* p) {
    return (uint32_t)__cvta_generic_to_shared(p);
}
__device__ __forceinline__ float ex2f(float x) {
    float r; asm("ex2.approx.f32 %0, %1;" : "=f"(r) : "f"(x)); return r;
}

#define MMA_F16(acc, a, b0, b1) \
    asm volatile("mma.sync.aligned.m16n8k16.row.col.f32.f16.f16.f32 " \
        "{%0,%1,%2,%3}, {%4,%5,%6,%7}, {%8,%9}, {%0,%1,%2,%3};" \
        : "+f"(acc[0]), "+f"(acc[1]), "+f"(acc[2]), "+f"(acc[3]) \
        : "r"(a[0]), "r"(a[1]), "r"(a[2]), "r"(a[3]), "r"(b0), "r"(b1))

#define MMA_BF16(acc, a, b0, b1) \
    asm volatile("mma.sync.aligned.m16n8k16.row.col.f32.bf16.bf16.f32 " \
        "{%0,%1,%2,%3}, {%4,%5,%6,%7}, {%8,%9}, {%0,%1,%2,%3};" \
        : "+f"(acc[0]), "+f"(acc[1]), "+f"(acc[2]), "+f"(acc[3]) \
        : "r"(a[0]), "r"(a[1]), "r"(a[2]), "r"(a[3]), "r"(b0), "r"(b1))

#define LDSM4(r, addr) \
    asm volatile("ldmatrix.sync.aligned.m8n8.x4.shared.b16 {%0,%1,%2,%3}, [%4];" \
        : "=r"(r[0]), "=r"(r[1]), "=r"(r[2]), "=r"(r[3]) : "r"(addr))

#define LDSM4T(r, addr) \
    asm volatile("ldmatrix.sync.aligned.m8n8.x4.trans.shared.b16 {%0,%1,%2,%3}, [%4];" \
        : "=r"(r[0]), "=r"(r[1]), "=r"(r[2]), "=r"(r[3]) : "r"(addr))

// ================= fp16 GEMM, R9 layout (words = fp16 pairs), K=32/chunk =================
#define TBM 128
#define TBN 128
#define GST 20   // 16 k-words + 4 pad per row (same proven layout as R9 tf32)

// epi: 0: (acc+bias)*mask[row]   1: acc+bias   2: A+relu(acc+bias)
__device__ __forceinline__ void gemm_body(
    const float* __restrict__ A, const float* __restrict__ W,
    const float* __restrict__ bias, const float* __restrict__ mask,
    float* __restrict__ Cf, __nv_bfloat16* __restrict__ Cb, const int epi,
    unsigned (*As)[TBM][GST], unsigned (*Bs)[TBN][GST])
{
    const int N = D_, K = D_;
    const int tid  = threadIdx.x;
    const int lane = tid & 31;
    const int wid  = tid >> 5;
    const int warp_m = (wid >> 1) * 32;
    const int warp_n = (wid & 1) * 64;
    const int bm = blockIdx.y * TBM;
    const int bn = blockIdx.x * TBN;
    const int gr = lane >> 2, gc = lane & 3;
    const int l7 = lane & 7;
    const int a_l8  = (lane & 8)  ? 8 : 0;
    const int a_l16 = (lane & 16) ? 4 : 0;
    const int b_l8  = (lane & 8)  ? 4 : 0;
    const int b_l16 = (lane & 16) ? 8 : 0;

    // A fill: rows (arow, arow+64), 8 consecutive k (two float4) -> 4 words fp16x2
    const int arow = tid >> 2;
    const int acol8 = (tid & 3) * 8;
    const float* Ap = A + (size_t)(bm + arow) * K + acol8;

    // B fill: column n = bnl, 16 consecutive k (kq2 selects k half) -> 8 words
    const int bnl  = tid & 127;
    const int kq2  = tid >> 7;            // 0 or 1: k offset 0 / 16
    const float* Wp = W + bn + bnl;

    float acc[2][8][4];
    #pragma unroll
    for (int mt = 0; mt < 2; mt++)
        #pragma unroll
        for (int nt = 0; nt < 8; nt++)
            #pragma unroll
            for (int c = 0; c < 4; c++) acc[mt][nt][c] = 0.f;

    uint4 aw0, aw1, bw0, bw1;

    // prefetch chunk 0 (converted to fp16 at load)
    {
        const float4 f0 = *(const float4*)(Ap);
        const float4 f1 = *(const float4*)(Ap + 4);
        const float4 f2 = *(const float4*)(Ap + (size_t)64 * K);
        const float4 f3 = *(const float4*)(Ap + (size_t)64 * K + 4);
        aw0 = make_uint4(pkhf(f0.x,f0.y), pkhf(f0.z,f0.w), pkhf(f1.x,f1.y), pkhf(f1.z,f1.w));
        aw1 = make_uint4(pkhf(f2.x,f2.y), pkhf(f2.z,f2.w), pkhf(f3.x,f3.y), pkhf(f3.z,f3.w));
        float b[16];
        #pragma unroll
        for (int j = 0; j < 16; j++) b[j] = Wp[(size_t)(kq2*16 + j) * N];
        bw0 = make_uint4(pkhf(b[0],b[1]), pkhf(b[2],b[3]), pkhf(b[4],b[5]), pkhf(b[6],b[7]));
        bw1 = make_uint4(pkhf(b[8],b[9]), pkhf(b[10],b[11]), pkhf(b[12],b[13]), pkhf(b[14],b[15]));
    }
    // store chunk 0
    *(uint4*)&As[0][arow][(tid & 3) * 4]    = aw0;
    *(uint4*)&As[0][arow+64][(tid & 3) * 4] = aw1;
    *(uint4*)&Bs[0][bnl][kq2 * 8]     = bw0;
    *(uint4*)&Bs[0][bnl][kq2 * 8 + 4] = bw1;
    __syncthreads();

    const int NT = K / 32;   // 16 chunks of K=32
    for (int t = 0; t < NT; t++) {
        const int buf = t & 1;
        if (t + 1 < NT) {
            const int k0 = (t + 1) * 32;
            const float4 f0 = *(const float4*)(Ap + k0);
            const float4 f1 = *(const float4*)(Ap + k0 + 4);
            const float4 f2 = *(const float4*)(Ap + (size_t)64 * K + k0);
            const float4 f3 = *(const float4*)(Ap + (size_t)64 * K + k0 + 4);
            aw0 = make_uint4(pkhf(f0.x,f0.y), pkhf(f0.z,f0.w), pkhf(f1.x,f1.y), pkhf(f1.z,f1.w));
            aw1 = make_uint4(pkhf(f2.x,f2.y), pkhf(f2.z,f2.w), pkhf(f3.x,f3.y), pkhf(f3.z,f3.w));
            float b[16];
            #pragma unroll
            for (int j = 0; j < 16; j++) b[j] = Wp[(size_t)(k0 + kq2*16 + j) * N];
            bw0 = make_uint4(pkhf(b[0],b[1]), pkhf(b[2],b[3]), pkhf(b[4],b[5]), pkhf(b[6],b[7]));
            bw1 = make_uint4(pkhf(b[8],b[9]), pkhf(b[10],b[11]), pkhf(b[12],b[13]), pkhf(b[14],b[15]));
        }

        #pragma unroll
        for (int ks = 0; ks < 2; ks++) {
            const int k0w = ks * 8;
            unsigned af[2][4], bf[4][4];
            #pragma unroll
            for (int mt = 0; mt < 2; mt++)
                LDSM4(af[mt], sptr(&As[buf][warp_m + mt*16 + a_l8 + l7][k0w + a_l16]));
            #pragma unroll
            for (int ntp = 0; ntp < 4; ntp++)
                LDSM4(bf[ntp], sptr(&Bs[buf][warp_n + ntp*16 + b_l16 + l7][k0w + b_l8]));
            #pragma unroll
            for (int mt = 0; mt < 2; mt++)
                #pragma unroll
                for (int nt = 0; nt < 8; nt++)
                    MMA_F16(acc[mt][nt], af[mt],
                            bf[nt>>1][(nt&1)*2], bf[nt>>1][(nt&1)*2+1]);
        }

        if (t + 1 < NT) {
            const int nb = (t + 1) & 1;
            *(uint4*)&As[nb][arow][(tid & 3) * 4]    = aw0;
            *(uint4*)&As[nb][arow+64][(tid & 3) * 4] = aw1;
            *(uint4*)&Bs[nb][bnl][kq2 * 8]     = bw0;
            *(uint4*)&Bs[nb][bnl][kq2 * 8 + 4] = bw1;
            __syncthreads();
        }
    }

    #pragma unroll
    for (int mt = 0; mt < 2; mt++) {
        #pragma unroll
        for (int nt = 0; nt < 8; nt++) {
            const int row0 = bm + warp_m + mt * 16 + gr;
            const int row1 = row0 + 8;
            const int col  = bn + warp_n + nt * 8 + gc * 2;
            const float b0 = bias[col], b1 = bias[col + 1];
            float v0 = acc[mt][nt][0] + b0;
            float v1 = acc[mt][nt][1] + b1;
            float v2 = acc[mt][nt][2] + b0;
            float v3 = acc[mt][nt][3] + b1;
            if (epi == 0) {
                const float m0 = mask[row0], m1 = mask[row1];
                v0 *= m0; v1 *= m0; v2 *= m1; v3 *= m1;
            } else if (epi == 2) {
                const float2 r0 = *(const float2*)(A + (size_t)row0 * K + col);
                const float2 r1 = *(const float2*)(A + (size_t)row1 * K + col);
                v0 = r0.x + fmaxf(v0, 0.f);
                v1 = r0.y + fmaxf(v1, 0.f);
                v2 = r1.x + fmaxf(v2, 0.f);
                v3 = r1.y + fmaxf(v3, 0.f);
            }
            if (Cf) {
                *(float2*)&Cf[(size_t)row0 * N + col] = make_float2(v0, v1);
                *(float2*)&Cf[(size_t)row1 * N + col] = make_float2(v2, v3);
            }
            if (Cb) {
                *(unsigned*)&Cb[(size_t)row0 * N + col] = pkbf(v0, v1);
                *(unsigned*)&Cb[(size_t)row1 * N + col] = pkbf(v2, v3);
            }
        }
    }
}

// merged 3-projection GEMM
__global__ void __launch_bounds__(256, 2) gemm3_k(
    const float* __restrict__ Q, const float* __restrict__ Kin,
    const float* __restrict__ Wq, const float* __restrict__ Wk,
    const float* __restrict__ Wv,
    const float* __restrict__ bq, const float* __restrict__ bk,
    const float* __restrict__ bv,
    const float* __restrict__ Qm, const float* __restrict__ Km,
    float* __restrict__ Qp,
    __nv_bfloat16* __restrict__ Qb, __nv_bfloat16* __restrict__ Kb,
    __nv_bfloat16* __restrict__ Vb)
{
    __shared__ unsigned As[2][TBM][GST];
    __shared__ unsigned Bs[2][TBN][GST];
    const int z = blockIdx.z;
    const float* A    = (z == 0) ? Q  : Kin;
    const float* W    = (z == 0) ? Wq : (z == 1) ? Wk : Wv;
    const float* bias = (z == 0) ? bq : (z == 1) ? bk : bv;
    const float* mask = (z == 0) ? Qm : Km;
    float* Cf         = (z == 0) ? Qp : nullptr;
    __nv_bfloat16* Cb = (z == 0) ? Qb : (z == 1) ? Kb : Vb;
    const int epi     = (z == 2) ? 1 : 0;
    gemm_body(A, W, bias, mask, Cf, Cb, epi, As, Bs);
}

__global__ void __launch_bounds__(256, 2) gemmo_k(
    const float* __restrict__ A, const float* __restrict__ W,
    const float* __restrict__ bias, float* __restrict__ C)
{
    __shared__ unsigned As[2][TBM][GST];
    __shared__ unsigned Bs[2][TBN][GST];
    gemm_body(A, W, bias, nullptr, C, nullptr, 2, As, Bs);
}

// ================= bf16 attention (R12: pre-converted operands + mask-in-exponent) =================
#define SH 72
#define ATT_SMEM ((128*SH + 2*64*SH + 2*64*SH)*2 + (128 + 2*64)*4)
#define C1_EXP 0.063758717f            // log2(e)/sqrt(512)
#define LOG2E  1.4426950408889634f

__global__ void __launch_bounds__(256, 2) attn_bf(
    const float* __restrict__ Qp, const __nv_bfloat16* __restrict__ Qbg,
    const __nv_bfloat16* __restrict__ Kbg, const __nv_bfloat16* __restrict__ Vbg,
    const float* __restrict__ Qm, const float* __restrict__ Km,
    float* __restrict__ O)
{
    extern __shared__ char smc[];
    __nv_bfloat16* Qs = (__nv_bfloat16*)smc;
    __nv_bfloat16* Ks = Qs + 128*SH;
    __nv_bfloat16* Vs = Ks + 2*64*SH;
    float* qms = (float*)(Vs + 2*64*SH);   // log2-domain query mask: 0 or -1e30
    float* kms = qms + 128;                // Km * log2e

    const int tid  = threadIdx.x;
    const int lane = tid & 31;
    const int wid  = tid >> 5;
    const int gr = lane >> 2, gc = lane & 3;
    const int l7  = lane & 7;
    const int l8  = (lane & 8)  ? 8 : 0;
    const int l16 = (lane & 16) ? 8 : 0;
    const int r0  = wid * 16;

    const int q0 = blockIdx.x * 128;
    const int b  = blockIdx.y;
    const int h  = blockIdx.z;
    const size_t base = (size_t)b * NQ * D_ + (size_t)h * DH;

    const int lrow = tid >> 4;
    const int lc4  = (tid & 15) * 4;

    #pragma unroll
    for (int p = 0; p < 8; p++) {
        const int row = p * 16 + lrow;
        *(uint2*)&Qs[row*SH + lc4] =
            *(const uint2*)(Qbg + base + (size_t)(q0 + row) * D_ + lc4);
    }
    if (tid < 128) qms[tid] = (Qm[(size_t)b*NQ + q0 + tid] > 0.5f) ? 0.f : -1e30f;

    uint2 kpre[4], vpre[4];
    #pragma unroll
    for (int p = 0; p < 4; p++) {
        const int row = p * 16 + lrow;
        kpre[p] = *(const uint2*)(Kbg + base + (size_t)row * D_ + lc4);
        vpre[p] = *(const uint2*)(Vbg + base + (size_t)row * D_ + lc4);
    }

    float oacc[8][4];
    #pragma unroll
    for (int nt = 0; nt < 8; nt++)
        #pragma unroll
        for (int c = 0; c < 4; c++) oacc[nt][c] = 0.f;
    float rsum0 = 0.f, rsum1 = 0.f;

    for (int kt = 0; kt < NQ/64; kt++) {
        const int buf = kt & 1;
        __nv_bfloat16* Kb = Ks + buf*64*SH;
        __nv_bfloat16* Vb = Vs + buf*64*SH;
        #pragma unroll
        for (int p = 0; p < 4; p++) {
            const int row = p * 16 + lrow;
            *(uint2*)&Kb[row*SH + lc4] = kpre[p];
            *(uint2*)&Vb[row*SH + lc4] = vpre[p];
        }
        if (tid < 64) kms[buf*64 + tid] = Km[(size_t)b*NQ + kt*64 + tid] * LOG2E;
        __syncthreads();

        if (kt + 1 < NQ/64) {
            #pragma unroll
            for (int p = 0; p < 4; p++)
                kpre[p] = *(const uint2*)(Kbg + base +
                    (size_t)((kt+1)*64 + p*16 + lrow) * D_ + lc4);
        }

        float sacc[8][4];
        #pragma unroll
        for (int nt = 0; nt < 8; nt++)
            #pragma unroll
            for (int c = 0; c < 4; c++) sacc[nt][c] = 0.f;

        #pragma unroll
        for (int ks = 0; ks < 4; ks++) {
            unsigned qf[4], bq[4][4];
            LDSM4(qf, sptr(&Qs[(r0 + l7 + l8)*SH + ks*16 + l16]));
            #pragma unroll
            for (int ntp = 0; ntp < 4; ntp++)
                LDSM4(bq[ntp], sptr(&Kb[(ntp*16 + l7 + l16)*SH + ks*16 + l8]));
            #pragma unroll
            for (int nt = 0; nt < 8; nt++)
                MMA_BF16(sacc[nt], qf, bq[nt>>1][(nt&1)*2], bq[nt>>1][(nt&1)*2+1]);
        }

        if (kt + 1 < NQ/64) {
            #pragma unroll
            for (int p = 0; p < 4; p++)
                vpre[p] = *(const uint2*)(Vbg + base +
                    (size_t)((kt+1)*64 + p*16 + lrow) * D_ + lc4);
        }

        unsigned xf[4][4];
        const float lg0 = qms[r0 + gr];
        const float lg1 = qms[r0 + 8 + gr];
        float p0 = 0.f, p1 = 0.f;
        #pragma unroll
        for (int nt = 0; nt < 8; nt++) {
            const int col = nt*8 + gc*2;
            const float km0 = kms[buf*64 + col];
            const float km1 = kms[buf*64 + col + 1];
            float y00 = ex2f(sacc[nt][0]*C1_EXP);
            float y01 = ex2f(sacc[nt][1]*C1_EXP);
            float y10 = ex2f(sacc[nt][2]*C1_EXP);
            float y11 = ex2f(sacc[nt][3]*C1_EXP);
            float x00 = ex2f(fmaf(y00, km0, lg0));
            float x01 = ex2f(fmaf(y01, km1, lg0));
            float x10 = ex2f(fmaf(y10, km0, lg1));
            float x11 = ex2f(fmaf(y11, km1, lg1));
            p0 += x00 + x01;
            p1 += x10 + x11;
            const int ksv = nt >> 1, pr = (nt & 1) * 2;
            xf[ksv][pr]     = pkbf(x00, x01);
            xf[ksv][pr + 1] = pkbf(x10, x11);
        }
        p0 += __shfl_xor_sync(0xffffffffu, p0, 1);
        p0 += __shfl_xor_sync(0xffffffffu, p0, 2);
        p1 += __shfl_xor_sync(0xffffffffu, p1, 1);
        p1 += __shfl_xor_sync(0xffffffffu, p1, 2);
        rsum0 += p0;
        rsum1 += p1;

        #pragma unroll
        for (int ksv = 0; ksv < 4; ksv++) {
            unsigned bv[4][4];
            #pragma unroll
            for (int ntp = 0; ntp < 4; ntp++)
                LDSM4T(bv[ntp], sptr(&Vb[(ksv*16 + l7 + l8)*SH + ntp*16 + l16]));
            #pragma unroll
            for (int nt = 0; nt < 8; nt++)
                MMA_BF16(oacc[nt], xf[ksv], bv[nt>>1][(nt&1)*2], bv[nt>>1][(nt&1)*2+1]);
        }
    }

    const float inv0 = 1.f / (rsum0 + 1e-8f);
    const float inv1 = 1.f / (rsum1 + 1e-8f);
    const int row0 = q0 + r0 + gr;
    const int row1 = row0 + 8;
    #pragma unroll
    for (int nt = 0; nt < 8; nt++) {
        const int col = nt*8 + gc*2;
        const float2 q0v = *(const float2*)(Qp + base + (size_t)row0*D_ + col);
        const float2 q1v = *(const float2*)(Qp + base + (size_t)row1*D_ + col);
        *(float2*)&O[base + (size_t)row0*D_ + col] =
            make_float2(q0v.x + oacc[nt][0]*inv0, q0v.y + oacc[nt][1]*inv0);
        *(float2*)&O[base + (size_t)row1*D_ + col] =
            make_float2(q1v.x + oacc[nt][2]*inv1, q1v.y + oacc[nt][3]*inv1);
    }
}

// ================= LayerNorm: warp per row =================
__global__ void __launch_bounds__(256) ln_w(
    const float* __restrict__ X, const float* __restrict__ g,
    const float* __restrict__ bb, float* __restrict__ Y)
{
    const int row  = blockIdx.x * 8 + (threadIdx.x >> 5);
    const int lane = threadIdx.x & 31;
    const float4* xr = (const float4*)(X + (size_t)row * D_);
    float4 v[4];
    float s = 0.f, s2 = 0.f;
    #pragma unroll
    for (int p = 0; p < 4; p++) {
        v[p] = xr[lane + 32*p];
        s  += v[p].x + v[p].y + v[p].z + v[p].w;
        s2 += v[p].x*v[p].x + v[p].y*v[p].y + v[p].z*v[p].z + v[p].w*v[p].w;
    }
    #pragma unroll
    for (int o = 16; o > 0; o >>= 1) {
        s  += __shfl_xor_sync(0xffffffffu, s,  o);
        s2 += __shfl_xor_sync(0xffffffffu, s2, o);
    }
    const float mean = s * (1.f/D_);
    const float var  = s2 * (1.f/D_) - mean*mean;
    const float inv  = rsqrtf(var + 1e-5f);
    float4* yr = (float4*)(Y + (size_t)row * D_);
    #pragma unroll
    for (int p = 0; p < 4; p++) {
        const float4 gv = ((const float4*)g)[lane + 32*p];
        const float4 bv = ((const float4*)bb)[lane + 32*p];
        float4 o;
        o.x = (v[p].x - mean)*inv*gv.x + bv.x;
        o.y = (v[p].y - mean)*inv*gv.y + bv.y;
        o.z = (v[p].z - mean)*inv*gv.z + bv.z;
        o.w = (v[p].w - mean)*inv*gv.w + bv.w;
        yr[lane + 32*p] = o;
    }
}

extern "C" void kernel_launch(void* const* d_in, const int* in_sizes, int n_in,
                              void* d_out, int out_size)
{
    const float* Q  = (const float*)d_in[0];
    const float* K  = (const float*)d_in[1];
    const float* Qm = (const float*)d_in[2];
    const float* Km = (const float*)d_in[3];
    const float* Wq = (const float*)d_in[4];
    const float* bq = (const float*)d_in[5];
    const float* Wk = (const float*)d_in[6];
    const float* bk = (const float*)d_in[7];
    const float* Wv = (const float*)d_in[8];
    const float* bv = (const float*)d_in[9];
    const float* Wo = (const float*)d_in[10];
    const float* bo = (const float*)d_in[11];
    const float* g0 = (const float*)d_in[12];
    const float* b0 = (const float*)d_in[13];
    const float* g1 = (const float*)d_in[14];
    const float* b1 = (const float*)d_in[15];
    float* out = (float*)d_out;

    float *pQp, *pO1, *pO2;
    __nv_bfloat16 *pQb, *pKb, *pVb;
    cudaGetSymbolAddress((void**)&pQp, g_Qp);
    cudaGetSymbolAddress((void**)&pO1, g_O1);
    cudaGetSymbolAddress((void**)&pO2, g_O2);
    cudaGetSymbolAddress((void**)&pQb, g_Qb);
    cudaGetSymbolAddress((void**)&pKb, g_Kb);
    cudaGetSymbolAddress((void**)&pVb, g_Vb);

    cudaFuncSetAttribute(attn_bf, cudaFuncAttributeMaxDynamicSharedMemorySize, ATT_SMEM);

    dim3 gblk(256);
    dim3 g3(D_/TBN, M_/TBM, 3);
    gemm3_k<<<g3, gblk>>>(Q, K, Wq, Wk, Wv, bq, bk, bv, Qm, Km, pQp, pQb, pKb, pVb);

    dim3 agrid(NQ/128, B_, H_);
    attn_bf<<<agrid, 256, ATT_SMEM>>>(pQp, pQb, pKb, pVb, Qm, Km, pO1);

    ln_w<<<M_/8, 256>>>(pO1, g0, b0, pO2);
    gemmo_k<<<dim3(D_/TBN, M_/TBM), gblk>>>(pO2, Wo, bo, pQp);
    ln_w<<<M_/8, 256>>>(pQp, g1, b1, out);
}